// round 4
// baseline (speedup 1.0000x reference)
#include <cuda_runtime.h>

#define HSTEP (1.0f/63.0f)

static __device__ float g_lsraw[128*64*231];
static __device__ float g_y[128*64*232];
static __device__ float g_dknot[63*232*128];
static __device__ float g_dmid [63*232*128];
static __device__ float g_z[128*256];
static __device__ float g_zmid[128*256];
static __device__ float g_a1[128*1024];
static __device__ float g_a2[128*256];
static __device__ float g_a3T[256*128];

__device__ __forceinline__ float2 ffma2(float2 a, float2 b, float2 c){
    unsigned long long au, bu, cu, du;
    au = *reinterpret_cast<unsigned long long*>(&a);
    bu = *reinterpret_cast<unsigned long long*>(&b);
    cu = *reinterpret_cast<unsigned long long*>(&c);
    asm("fma.rn.f32x2 %0,%1,%2,%3;" : "=l"(du) : "l"(au), "l"(bu), "l"(cu));
    return *reinterpret_cast<float2*>(&du);
}

__device__ __forceinline__ void block_reduce_sum2(float& s, float& q){
    __shared__ float sh[64];
    const unsigned m = 0xffffffffu;
    #pragma unroll
    for (int off = 16; off; off >>= 1){
        s += __shfl_down_sync(m, s, off);
        q += __shfl_down_sync(m, q, off);
    }
    int w = threadIdx.x >> 5, l = threadIdx.x & 31;
    if (l == 0){ sh[w] = s; sh[32+w] = q; }
    __syncthreads();
    if (threadIdx.x == 0){
        float ts = 0.f, tq = 0.f;
        int nw = blockDim.x >> 5;
        for (int i = 0; i < nw; i++){ ts += sh[i]; tq += sh[32+i]; }
        sh[0] = ts; sh[32] = tq;
    }
    __syncthreads();
    s = sh[0]; q = sh[32];
}

// ---- 1) depth-2 log-signature of time-augmented path (raw) ----
__global__ void k_logsig(const float* __restrict__ x){
    int b = blockIdx.x;
    __shared__ float psh[64*21];
    for (int idx = threadIdx.x; idx < 64*21; idx += blockDim.x){
        int n = idx / 21, i = idx % 21;
        psh[idx] = (i == 0) ? (float)n * HSTEP : x[(b*64 + n)*20 + (i-1)];
    }
    __syncthreads();
    int ch = threadIdx.x;
    if (ch < 21){
        for (int n = 0; n < 64; n++)
            g_lsraw[((size_t)b*64 + n)*231 + ch] = psh[n*21 + ch];
    } else if (ch < 231){
        int pp = ch - 21, i = 0, rem = pp;
        while (rem >= 20 - i){ rem -= 20 - i; i++; }
        int j = i + 1 + rem;
        float acc = 0.f, pip = 0.f, pjp = 0.f;
        for (int n = 0; n < 64; n++){
            float pi = psh[n*21 + i], pj = psh[n*21 + j];
            acc += 0.5f*(pip*(pj - pjp) - (pi - pip)*pjp);
            g_lsraw[((size_t)b*64 + n)*231 + ch] = acc;
            pip = pi; pjp = pj;
        }
    }
}

// ---- 2) sig_norm LN + time-augmented control y ----
__global__ void k_lnorm(const float* __restrict__ sg, const float* __restrict__ sb){
    int r = blockIdx.x, t = threadIdx.x;
    float v = (t < 231) ? g_lsraw[(size_t)r*231 + t] : 0.f;
    float s = v, q = v*v;
    block_reduce_sum2(s, q);
    float mean = s*(1.0f/231.0f);
    float var  = q*(1.0f/231.0f) - mean*mean;
    float rstd = rsqrtf(var + 1e-5f);
    if (t < 231) g_y[(size_t)r*232 + 1 + t] = (v - mean)*rstd*sg[t] + sb[t];
    if (t == 0)  g_y[(size_t)r*232] = (float)(r & 63) * HSTEP;
}

// ---- 3) natural cubic spline derivatives ----
__global__ void k_spline(){
    __shared__ float cpS[64], idS[64];
    int t = threadIdx.x;
    if (t == 0){
        double ad = (1.0/63.0)/6.0, bd = 2.0*(1.0/63.0)/3.0, cprev = 0.0;
        for (int i = 1; i <= 62; i++){
            double den = bd - ad*cprev, cp = ad/den;
            cpS[i] = (float)cp; idS[i] = (float)(1.0/den); cprev = cp;
        }
    }
    __syncthreads();
    int g = blockIdx.x*128 + t;
    int b = g / 232, c = g % 232;
    float yv[64], M[64];
    for (int n = 0; n < 64; n++) yv[n] = g_y[((size_t)b*64 + n)*232 + c];
    const float ad = HSTEP/6.0f;
    M[0] = 0.f; M[63] = 0.f;
    float prev = 0.f;
    for (int i = 1; i <= 62; i++){
        float rhs = (yv[i+1] - 2.f*yv[i] + yv[i-1]) * 63.0f;
        prev = (rhs - ad*prev) * idS[i];
        M[i] = prev;
    }
    for (int i = 61; i >= 1; i--) M[i] -= cpS[i]*M[i+1];
    for (int n = 0; n < 63; n++){
        float dy = (yv[n+1] - yv[n]) * 63.0f;
        size_t o = ((size_t)n*232 + c)*128 + b;
        g_dknot[o] = dy - (HSTEP/6.0f) *(2.f*M[n] + M[n+1]);
        g_dmid [o] = dy + (HSTEP/24.0f)*(M[n] - M[n+1]);
    }
}

// ---- 4) initial hidden state ----
__global__ void k_h0(const float* __restrict__ x,  const float* __restrict__ hW1,
                     const float* __restrict__ hb1, const float* __restrict__ hW2,
                     const float* __restrict__ hb2){
    int b = blockIdx.x, t = threadIdx.x;
    __shared__ float x0[20];
    __shared__ float hid[256];
    if (t < 20) x0[t] = x[(size_t)b*64*20 + t];
    __syncthreads();
    float s = hb1[t];
    for (int d = 0; d < 20; d++) s = fmaf(x0[d], hW1[d*256 + t], s);
    hid[t] = fmaxf(s, 0.f);
    __syncthreads();
    float s2 = hb2[t];
    for (int k = 0; k < 256; k++) s2 = fmaf(hid[k], hW2[k*256 + t], s2);
    g_z[b*256 + t] = s2;
}

// ---- generic tiled GEMM: out[16b x 64n] tiles, optional relu+transpose ----
__global__ void __launch_bounds__(256) k_gemm(
    const float* __restrict__ in, const float* __restrict__ W,
    const float* __restrict__ bias, float* __restrict__ out,
    int K, int Nout, int mode)
{
    __shared__ float wsh[2048];
    __shared__ float ish[512];
    int n0 = blockIdx.x*64, b0 = blockIdx.y*16;
    int t = threadIdx.x, bi = t >> 4, ng = t & 15;
    float4 acc = *(const float4*)(bias + n0 + ng*4);
    for (int k0 = 0; k0 < K; k0 += 32){
        __syncthreads();
        #pragma unroll
        for (int j = 0; j < 8; j++){
            int e = t + j*256;
            wsh[e] = W[(size_t)(k0 + (e >> 6))*Nout + n0 + (e & 63)];
        }
        #pragma unroll
        for (int j = 0; j < 2; j++){
            int e = t + j*256;
            ish[e] = in[(size_t)(b0 + (e >> 5))*K + k0 + (e & 31)];
        }
        __syncthreads();
        #pragma unroll
        for (int kk = 0; kk < 32; kk++){
            float zv = ish[bi*32 + kk];
            float4 w = *(const float4*)(wsh + kk*64 + ng*4);
            acc.x = fmaf(zv, w.x, acc.x); acc.y = fmaf(zv, w.y, acc.y);
            acc.z = fmaf(zv, w.z, acc.z); acc.w = fmaf(zv, w.w, acc.w);
        }
    }
    if (mode){
        int n = n0 + ng*4, bb = b0 + bi;
        out[(size_t)(n+0)*128 + bb] = fmaxf(acc.x, 0.f);
        out[(size_t)(n+1)*128 + bb] = fmaxf(acc.y, 0.f);
        out[(size_t)(n+2)*128 + bb] = fmaxf(acc.z, 0.f);
        out[(size_t)(n+3)*128 + bb] = fmaxf(acc.w, 0.f);
    } else {
        *(float4*)(out + (size_t)(b0 + bi)*Nout + n0 + ng*4) = acc;
    }
}

// ---- LayerNorm + relu, in place, width 256 or 1024 ----
__global__ void k_ln(float* __restrict__ buf, const float* __restrict__ gw,
                     const float* __restrict__ bw, int W){
    int b = blockIdx.x, t = threadIdx.x, nv = W >> 8;
    float v[4];
    float s = 0.f, q = 0.f;
    #pragma unroll
    for (int i = 0; i < 4; i++) if (i < nv){
        v[i] = buf[(size_t)b*W + i*256 + t]; s += v[i]; q += v[i]*v[i];
    }
    block_reduce_sum2(s, q);
    float inv = 1.0f/(float)W;
    float mean = s*inv, var = q*inv - mean*mean;
    float rstd = rsqrtf(var + 1e-5f);
    #pragma unroll
    for (int i = 0; i < 4; i++) if (i < nv){
        int idx = i*256 + t;
        buf[(size_t)b*W + idx] = fmaxf((v[i]-mean)*rstd*gw[idx] + bw[idx], 0.f);
    }
}

// ---- hot contraction + z update: block per h, dX half-rows in registers ----
__global__ void __launch_bounds__(256,1) k_g(
    const float* __restrict__ fW4, const float* __restrict__ fb4,
    const float* __restrict__ dX, const float* __restrict__ zbase,
    float* __restrict__ zout, float coef)
{
    int h = blockIdx.x, tid = threadIdx.x;
    int half = tid & 1, b = tid >> 1;
    __shared__ float2 wsh[2][116];
    float2 dreg[58];
    const float* dbase = dX + (size_t)(half*116)*128 + b;
    #pragma unroll
    for (int i = 0; i < 58; i++)
        dreg[i] = make_float2(__ldg(dbase + (2*i)*128), __ldg(dbase + (2*i+1)*128));
    const float* a3p = g_a3T + b;
    const float* wrow0 = fW4 + (size_t)h*232;
    float2 acc = make_float2(0.f, 0.f);
    float2 wpre = make_float2(0.f, 0.f);
    if (tid < 116) wpre = __ldg((const float2*)wrow0 + tid);
    for (int k = 0; k < 257; k++){
        __syncthreads();
        if (tid < 116) wsh[k & 1][tid] = wpre;
        if (k < 256 && tid < 116){
            const float* nrow = (k == 255) ? (fb4 + (size_t)h*232)
                                           : (wrow0 + (size_t)(k+1)*59392);
            wpre = __ldg((const float2*)nrow + tid);
        }
        float a3v = (k < 256) ? __ldg(a3p + k*128) : 1.0f;
        __syncthreads();
        const float2* wc = wsh[k & 1] + half*58;
        float2 dot = make_float2(0.f, 0.f);
        #pragma unroll
        for (int i = 0; i < 58; i++) dot = ffma2(dreg[i], wc[i], dot);
        acc = ffma2(make_float2(a3v, a3v), dot, acc);
    }
    float s = acc.x + acc.y;
    s += __shfl_xor_sync(0xffffffffu, s, 1);
    if (half == 0) zout[b*256 + h] = zbase[b*256 + h] + coef*s;
}

// ---- output heads: Y, Z, hT ----
__global__ void k_head(const float* __restrict__ yW1, const float* __restrict__ yb1,
                       const float* __restrict__ yW2, const float* __restrict__ yb2,
                       const float* __restrict__ zW1, const float* __restrict__ zb1,
                       const float* __restrict__ zW2, const float* __restrict__ zb2,
                       float* __restrict__ out){
    int b = blockIdx.x, t = threadIdx.x;
    __shared__ float hsh[256], t1[128], t2[256];
    hsh[t] = g_z[b*256 + t];
    __syncthreads();
    float s = zb1[t];
    for (int k = 0; k < 256; k++) s = fmaf(hsh[k], zW1[k*256 + t], s);
    t2[t] = fmaxf(s, 0.f);
    if (t < 128){
        float s1 = yb1[t];
        for (int k = 0; k < 256; k++) s1 = fmaf(hsh[k], yW1[k*128 + t], s1);
        t1[t] = fmaxf(s1, 0.f);
    }
    __syncthreads();
    if (t == 0){
        float y = yb2[0];
        for (int j = 0; j < 128; j++) y = fmaf(t1[j], yW2[j], y);
        out[b] = y;
    }
    if (t < 20){
        float zz = zb2[t];
        for (int k = 0; k < 256; k++) zz = fmaf(t2[k], zW2[k*20 + t], zz);
        out[128 + b*20 + t] = zz;
    }
    out[128 + 2560 + b*256 + t] = hsh[t];
}

extern "C" void kernel_launch(void* const* d_in, const int* in_sizes, int n_in,
                              void* d_out, int out_size){
    const float* x  =(const float*)d_in[0];
    const float* hW1=(const float*)d_in[1]; const float* hb1=(const float*)d_in[2];
    const float* hW2=(const float*)d_in[3]; const float* hb2=(const float*)d_in[4];
    const float* fW1=(const float*)d_in[5]; const float* fb1=(const float*)d_in[6];
    const float* g1 =(const float*)d_in[7]; const float* be1=(const float*)d_in[8];
    const float* fW2=(const float*)d_in[9]; const float* fb2=(const float*)d_in[10];
    const float* g2 =(const float*)d_in[11]; const float* be2=(const float*)d_in[12];
    const float* fW3=(const float*)d_in[13]; const float* fb3=(const float*)d_in[14];
    const float* fW4=(const float*)d_in[15]; const float* fb4=(const float*)d_in[16];
    const float* yW1=(const float*)d_in[17]; const float* yb1=(const float*)d_in[18];
    const float* yW2=(const float*)d_in[19]; const float* yb2=(const float*)d_in[20];
    const float* zW1=(const float*)d_in[21]; const float* zb1=(const float*)d_in[22];
    const float* zW2=(const float*)d_in[23]; const float* zb2=(const float*)d_in[24];
    const float* sg =(const float*)d_in[25]; const float* sb =(const float*)d_in[26];
    float* out = (float*)d_out;

    float *p_z, *p_zmid, *p_a1, *p_a2, *p_a3T, *p_dk, *p_dm;
    cudaGetSymbolAddress((void**)&p_z,    g_z);
    cudaGetSymbolAddress((void**)&p_zmid, g_zmid);
    cudaGetSymbolAddress((void**)&p_a1,   g_a1);
    cudaGetSymbolAddress((void**)&p_a2,   g_a2);
    cudaGetSymbolAddress((void**)&p_a3T,  g_a3T);
    cudaGetSymbolAddress((void**)&p_dk,   g_dknot);
    cudaGetSymbolAddress((void**)&p_dm,   g_dmid);

    k_logsig<<<128, 256>>>(x);
    k_lnorm <<<8192, 256>>>(sg, sb);
    k_spline<<<232, 128>>>();
    k_h0    <<<128, 256>>>(x, hW1, hb1, hW2, hb2);

    for (int n = 0; n < 63; n++){
        const float* dk = p_dk + (size_t)n*232*128;
        const float* dm = p_dm + (size_t)n*232*128;
        // eval 1: k1 = g(z, d_knot); zmid = z + 0.5h k1
        k_gemm<<<dim3(16,8), 256>>>(p_z, fW1, fb1, p_a1, 256, 1024, 0);
        k_ln  <<<128, 256>>>(p_a1, g1, be1, 1024);
        k_gemm<<<dim3(4,8), 256>>>(p_a1, fW2, fb2, p_a2, 1024, 256, 0);
        k_ln  <<<128, 256>>>(p_a2, g2, be2, 256);
        k_gemm<<<dim3(4,8), 256>>>(p_a2, fW3, fb3, p_a3T, 256, 256, 1);
        k_g   <<<256, 256>>>(fW4, fb4, dk, p_z, p_zmid, 0.5f*HSTEP);
        // eval 2: z = z + h * g(zmid, d_mid)
        k_gemm<<<dim3(16,8), 256>>>(p_zmid, fW1, fb1, p_a1, 256, 1024, 0);
        k_ln  <<<128, 256>>>(p_a1, g1, be1, 1024);
        k_gemm<<<dim3(4,8), 256>>>(p_a1, fW2, fb2, p_a2, 1024, 256, 0);
        k_ln  <<<128, 256>>>(p_a2, g2, be2, 256);
        k_gemm<<<dim3(4,8), 256>>>(p_a2, fW3, fb3, p_a3T, 256, 256, 1);
        k_g   <<<256, 256>>>(fW4, fb4, dm, p_z, p_z, HSTEP);
    }
    k_head<<<128, 256>>>(yW1, yb1, yW2, yb2, zW1, zb1, zW2, zb2, out);
}

// round 5
// speedup vs baseline: 1.4158x; 1.4158x over previous
#include <cuda_runtime.h>

#define HSTEP (1.0f/63.0f)
#define KH4 59392

static __device__ float g_lsraw[128*64*231];
static __device__ float g_y[128*64*232];
static __device__ float g_dknot[63*232*128];
static __device__ float g_dmid [63*232*128];
static __device__ float g_z[128*256];
static __device__ float g_zmid[128*256];
static __device__ float g_a1[128*1024];
static __device__ float g_a2[128*256];
static __device__ float g_a3T[256*128];

__device__ __forceinline__ float2 ffma2(float2 a, float2 b, float2 c){
    unsigned long long au, bu, cu, du;
    au = *reinterpret_cast<unsigned long long*>(&a);
    bu = *reinterpret_cast<unsigned long long*>(&b);
    cu = *reinterpret_cast<unsigned long long*>(&c);
    asm("fma.rn.f32x2 %0,%1,%2,%3;" : "=l"(du) : "l"(au), "l"(bu), "l"(cu));
    return *reinterpret_cast<float2*>(&du);
}

__device__ __forceinline__ void block_reduce_sum2(float& s, float& q){
    __shared__ float sh[64];
    const unsigned m = 0xffffffffu;
    #pragma unroll
    for (int off = 16; off; off >>= 1){
        s += __shfl_down_sync(m, s, off);
        q += __shfl_down_sync(m, q, off);
    }
    int w = threadIdx.x >> 5, l = threadIdx.x & 31;
    if (l == 0){ sh[w] = s; sh[32+w] = q; }
    __syncthreads();
    if (threadIdx.x == 0){
        float ts = 0.f, tq = 0.f;
        int nw = blockDim.x >> 5;
        for (int i = 0; i < nw; i++){ ts += sh[i]; tq += sh[32+i]; }
        sh[0] = ts; sh[32] = tq;
    }
    __syncthreads();
    s = sh[0]; q = sh[32];
}

// ---- 1) depth-2 log-signature of time-augmented path (raw) ----
__global__ void k_logsig(const float* __restrict__ x){
    int b = blockIdx.x;
    __shared__ float psh[64*21];
    for (int idx = threadIdx.x; idx < 64*21; idx += blockDim.x){
        int n = idx / 21, i = idx % 21;
        psh[idx] = (i == 0) ? (float)n * HSTEP : x[(b*64 + n)*20 + (i-1)];
    }
    __syncthreads();
    int ch = threadIdx.x;
    if (ch < 21){
        for (int n = 0; n < 64; n++)
            g_lsraw[((size_t)b*64 + n)*231 + ch] = psh[n*21 + ch];
    } else if (ch < 231){
        int pp = ch - 21, i = 0, rem = pp;
        while (rem >= 20 - i){ rem -= 20 - i; i++; }
        int j = i + 1 + rem;
        float acc = 0.f, pip = 0.f, pjp = 0.f;
        for (int n = 0; n < 64; n++){
            float pi = psh[n*21 + i], pj = psh[n*21 + j];
            acc += 0.5f*(pip*(pj - pjp) - (pi - pip)*pjp);
            g_lsraw[((size_t)b*64 + n)*231 + ch] = acc;
            pip = pi; pjp = pj;
        }
    }
}

// ---- 2) sig_norm LN + time-augmented control y ----
__global__ void k_lnorm(const float* __restrict__ sg, const float* __restrict__ sb){
    int r = blockIdx.x, t = threadIdx.x;
    float v = (t < 231) ? g_lsraw[(size_t)r*231 + t] : 0.f;
    float s = v, q = v*v;
    block_reduce_sum2(s, q);
    float mean = s*(1.0f/231.0f);
    float var  = q*(1.0f/231.0f) - mean*mean;
    float rstd = rsqrtf(var + 1e-5f);
    if (t < 231) g_y[(size_t)r*232 + 1 + t] = (v - mean)*rstd*sg[t] + sb[t];
    if (t == 0)  g_y[(size_t)r*232] = (float)(r & 63) * HSTEP;
}

// ---- 3) natural cubic spline derivatives ----
__global__ void k_spline(){
    __shared__ float cpS[64], idS[64];
    int t = threadIdx.x;
    if (t == 0){
        double ad = (1.0/63.0)/6.0, bd = 2.0*(1.0/63.0)/3.0, cprev = 0.0;
        for (int i = 1; i <= 62; i++){
            double den = bd - ad*cprev, cp = ad/den;
            cpS[i] = (float)cp; idS[i] = (float)(1.0/den); cprev = cp;
        }
    }
    __syncthreads();
    int g = blockIdx.x*128 + t;
    int b = g / 232, c = g % 232;
    float yv[64], M[64];
    for (int n = 0; n < 64; n++) yv[n] = g_y[((size_t)b*64 + n)*232 + c];
    const float ad = HSTEP/6.0f;
    M[0] = 0.f; M[63] = 0.f;
    float prev = 0.f;
    for (int i = 1; i <= 62; i++){
        float rhs = (yv[i+1] - 2.f*yv[i] + yv[i-1]) * 63.0f;
        prev = (rhs - ad*prev) * idS[i];
        M[i] = prev;
    }
    for (int i = 61; i >= 1; i--) M[i] -= cpS[i]*M[i+1];
    for (int n = 0; n < 63; n++){
        float dy = (yv[n+1] - yv[n]) * 63.0f;
        size_t o = ((size_t)n*232 + c)*128 + b;
        g_dknot[o] = dy - (HSTEP/6.0f) *(2.f*M[n] + M[n+1]);
        g_dmid [o] = dy + (HSTEP/24.0f)*(M[n] - M[n+1]);
    }
}

// ---- 4) initial hidden state ----
__global__ void k_h0(const float* __restrict__ x,  const float* __restrict__ hW1,
                     const float* __restrict__ hb1, const float* __restrict__ hW2,
                     const float* __restrict__ hb2){
    int b = blockIdx.x, t = threadIdx.x;
    __shared__ float x0[20];
    __shared__ float hid[256];
    if (t < 20) x0[t] = x[(size_t)b*64*20 + t];
    __syncthreads();
    float s = hb1[t];
    for (int d = 0; d < 20; d++) s = fmaf(x0[d], hW1[d*256 + t], s);
    hid[t] = fmaxf(s, 0.f);
    __syncthreads();
    float s2 = hb2[t];
    for (int k = 0; k < 256; k++) s2 = fmaf(hid[k], hW2[k*256 + t], s2);
    g_z[b*256 + t] = s2;
}

// ---- generic tiled GEMM: out[16b x 64n] tiles, optional relu+transpose ----
__global__ void __launch_bounds__(256) k_gemm(
    const float* __restrict__ in, const float* __restrict__ W,
    const float* __restrict__ bias, float* __restrict__ out,
    int K, int Nout, int mode)
{
    __shared__ float wsh[2048];
    __shared__ float ish[512];
    int n0 = blockIdx.x*64, b0 = blockIdx.y*16;
    int t = threadIdx.x, bi = t >> 4, ng = t & 15;
    float4 bia = *(const float4*)(bias + n0 + ng*4);
    float2 acc0 = make_float2(bia.x, bia.y);
    float2 acc1 = make_float2(bia.z, bia.w);
    for (int k0 = 0; k0 < K; k0 += 32){
        __syncthreads();
        #pragma unroll
        for (int j = 0; j < 8; j++){
            int e = t + j*256;
            wsh[e] = W[(size_t)(k0 + (e >> 6))*Nout + n0 + (e & 63)];
        }
        #pragma unroll
        for (int j = 0; j < 2; j++){
            int e = t + j*256;
            ish[e] = in[(size_t)(b0 + (e >> 5))*K + k0 + (e & 31)];
        }
        __syncthreads();
        #pragma unroll
        for (int kk = 0; kk < 32; kk++){
            float zv = ish[bi*32 + kk];
            float2 zz = make_float2(zv, zv);
            const float2* wp = (const float2*)(wsh + kk*64 + ng*4);
            acc0 = ffma2(zz, wp[0], acc0);
            acc1 = ffma2(zz, wp[1], acc1);
        }
    }
    if (mode){
        int n = n0 + ng*4, bb = b0 + bi;
        out[(size_t)(n+0)*128 + bb] = fmaxf(acc0.x, 0.f);
        out[(size_t)(n+1)*128 + bb] = fmaxf(acc0.y, 0.f);
        out[(size_t)(n+2)*128 + bb] = fmaxf(acc1.x, 0.f);
        out[(size_t)(n+3)*128 + bb] = fmaxf(acc1.y, 0.f);
    } else {
        float4 o = make_float4(acc0.x, acc0.y, acc1.x, acc1.y);
        *(float4*)(out + (size_t)(b0 + bi)*Nout + n0 + ng*4) = o;
    }
}

// ---- LayerNorm + relu, in place, width 256 or 1024 ----
__global__ void k_ln(float* __restrict__ buf, const float* __restrict__ gw,
                     const float* __restrict__ bw, int W){
    int b = blockIdx.x, t = threadIdx.x, nv = W >> 8;
    float v[4];
    float s = 0.f, q = 0.f;
    #pragma unroll
    for (int i = 0; i < 4; i++) if (i < nv){
        v[i] = buf[(size_t)b*W + i*256 + t]; s += v[i]; q += v[i]*v[i];
    }
    block_reduce_sum2(s, q);
    float inv = 1.0f/(float)W;
    float mean = s*inv, var = q*inv - mean*mean;
    float rstd = rsqrtf(var + 1e-5f);
    #pragma unroll
    for (int i = 0; i < 4; i++) if (i < nv){
        int idx = i*256 + t;
        buf[(size_t)b*W + idx] = fmaxf((v[i]-mean)*rstd*gw[idx] + bw[idx], 0.f);
    }
}

// ---- hot contraction as register-tiled GEMM + fused dX dot + z update ----
// block = one h (grid 256). 256 threads = 16 bt x 16 ct.
// V[128b x 232c] = a3(128x256) @ fW4[:, h*232 .. +232], thread tile 8b x 16c
// (c as 8 float2 pairs, pair j at c = ct*2 + j*32). Epilogue: += fb4 row,
// dot with dX[b, c], reduce over ct, z update.
__global__ void __launch_bounds__(256) k_g(
    const float* __restrict__ fW4, const float* __restrict__ fb4,
    const float* __restrict__ dX, const float* __restrict__ zbase,
    float* __restrict__ zout, float coef)
{
    __shared__ float Ws[2][16*260];
    __shared__ float red[16*128];
    const int h = blockIdx.x, t = threadIdx.x;
    const int ct = t & 15, bt = t >> 4;
    const int kr = t >> 4, lane = t & 15;
    const float* wbase = fW4 + (size_t)h*232;

    // zero pad columns [232,260) of both buffers (written once, never touched)
    for (int e = t; e < 16*28*2; e += 256){
        int bufi = e / (16*28); int r = (e/28) & 15; int cc = 232 + (e % 28);
        Ws[bufi][r*260 + cc] = 0.f;
    }
    // stage k-tile 0: rows kr (16), 58 float4 per row by 16 lanes x 4
    #pragma unroll
    for (int m = 0; m < 4; m++){
        int idx = lane + 16*m;
        if (idx < 58){
            float4 v = __ldg((const float4*)(wbase + (size_t)kr*KH4) + idx);
            *(float4*)&Ws[0][kr*260 + idx*4] = v;
        }
    }
    __syncthreads();

    float2 acc[8][8];
    #pragma unroll
    for (int i = 0; i < 8; i++)
        #pragma unroll
        for (int j = 0; j < 8; j++) acc[i][j] = make_float2(0.f, 0.f);

    const float* a3b = g_a3T + bt*8;

    for (int kt = 0; kt < 16; kt++){
        const int buf = kt & 1;
        float4 pre[4];
        if (kt < 15){
            const float* rb = wbase + (size_t)((kt+1)*16 + kr)*KH4;
            #pragma unroll
            for (int m = 0; m < 4; m++){
                int idx = lane + 16*m;
                pre[m] = (idx < 58) ? __ldg((const float4*)rb + idx)
                                    : make_float4(0.f,0.f,0.f,0.f);
            }
        }
        #pragma unroll
        for (int kk = 0; kk < 16; kk++){
            int k = kt*16 + kk;
            float4 a0 = __ldg((const float4*)(a3b + k*128));
            float4 a1 = __ldg((const float4*)(a3b + k*128) + 1);
            float2 w[8];
            #pragma unroll
            for (int j = 0; j < 8; j++)
                w[j] = *(const float2*)&Ws[buf][kk*260 + ct*2 + j*32];
            float av[8] = {a0.x, a0.y, a0.z, a0.w, a1.x, a1.y, a1.z, a1.w};
            #pragma unroll
            for (int i = 0; i < 8; i++){
                float2 ad = make_float2(av[i], av[i]);
                #pragma unroll
                for (int j = 0; j < 8; j++)
                    acc[i][j] = ffma2(ad, w[j], acc[i][j]);
            }
        }
        if (kt < 15){
            #pragma unroll
            for (int m = 0; m < 4; m++){
                int idx = lane + 16*m;
                if (idx < 58) *(float4*)&Ws[buf^1][kr*260 + idx*4] = pre[m];
            }
            __syncthreads();
        }
    }

    // bias row (vf output adds fb4 per (h,c) before dX contraction)
    #pragma unroll
    for (int j = 0; j < 8; j++){
        int c0 = ct*2 + j*32;
        if (c0 < 232){
            float2 wb = *(const float2*)(fb4 + (size_t)h*232 + c0);
            #pragma unroll
            for (int i = 0; i < 8; i++){
                acc[i][j].x += wb.x; acc[i][j].y += wb.y;
            }
        }
    }
    // dot with dX (layout [c][128 b])
    float part[8];
    #pragma unroll
    for (int i = 0; i < 8; i++) part[i] = 0.f;
    #pragma unroll
    for (int j = 0; j < 8; j++){
        int c0 = ct*2 + j*32;
        if (c0 < 232){
            const float* dx0 = dX + (size_t)c0*128 + bt*8;
            const float* dx1 = dx0 + 128;
            #pragma unroll
            for (int i = 0; i < 8; i++)
                part[i] += acc[i][j].x * __ldg(dx0 + i)
                         + acc[i][j].y * __ldg(dx1 + i);
        }
    }
    #pragma unroll
    for (int i = 0; i < 8; i++) red[ct*128 + bt*8 + i] = part[i];
    __syncthreads();
    if (t < 128){
        float s = 0.f;
        #pragma unroll
        for (int r = 0; r < 16; r++) s += red[r*128 + t];
        zout[t*256 + h] = zbase[t*256 + h] + coef*s;
    }
}

// ---- output heads: Y, Z, hT ----
__global__ void k_head(const float* __restrict__ yW1, const float* __restrict__ yb1,
                       const float* __restrict__ yW2, const float* __restrict__ yb2,
                       const float* __restrict__ zW1, const float* __restrict__ zb1,
                       const float* __restrict__ zW2, const float* __restrict__ zb2,
                       float* __restrict__ out){
    int b = blockIdx.x, t = threadIdx.x;
    __shared__ float hsh[256], t1[128], t2[256];
    hsh[t] = g_z[b*256 + t];
    __syncthreads();
    float s = zb1[t];
    for (int k = 0; k < 256; k++) s = fmaf(hsh[k], zW1[k*256 + t], s);
    t2[t] = fmaxf(s, 0.f);
    if (t < 128){
        float s1 = yb1[t];
        for (int k = 0; k < 256; k++) s1 = fmaf(hsh[k], yW1[k*128 + t], s1);
        t1[t] = fmaxf(s1, 0.f);
    }
    __syncthreads();
    if (t == 0){
        float y = yb2[0];
        for (int j = 0; j < 128; j++) y = fmaf(t1[j], yW2[j], y);
        out[b] = y;
    }
    if (t < 20){
        float zz = zb2[t];
        for (int k = 0; k < 256; k++) zz = fmaf(t2[k], zW2[k*20 + t], zz);
        out[128 + b*20 + t] = zz;
    }
    out[128 + 2560 + b*256 + t] = hsh[t];
}

extern "C" void kernel_launch(void* const* d_in, const int* in_sizes, int n_in,
                              void* d_out, int out_size){
    const float* x  =(const float*)d_in[0];
    const float* hW1=(const float*)d_in[1]; const float* hb1=(const float*)d_in[2];
    const float* hW2=(const float*)d_in[3]; const float* hb2=(const float*)d_in[4];
    const float* fW1=(const float*)d_in[5]; const float* fb1=(const float*)d_in[6];
    const float* g1 =(const float*)d_in[7]; const float* be1=(const float*)d_in[8];
    const float* fW2=(const float*)d_in[9]; const float* fb2=(const float*)d_in[10];
    const float* g2 =(const float*)d_in[11]; const float* be2=(const float*)d_in[12];
    const float* fW3=(const float*)d_in[13]; const float* fb3=(const float*)d_in[14];
    const float* fW4=(const float*)d_in[15]; const float* fb4=(const float*)d_in[16];
    const float* yW1=(const float*)d_in[17]; const float* yb1=(const float*)d_in[18];
    const float* yW2=(const float*)d_in[19]; const float* yb2=(const float*)d_in[20];
    const float* zW1=(const float*)d_in[21]; const float* zb1=(const float*)d_in[22];
    const float* zW2=(const float*)d_in[23]; const float* zb2=(const float*)d_in[24];
    const float* sg =(const float*)d_in[25]; const float* sb =(const float*)d_in[26];
    float* out = (float*)d_out;

    float *p_z, *p_zmid, *p_a1, *p_a2, *p_a3T, *p_dk, *p_dm;
    cudaGetSymbolAddress((void**)&p_z,    g_z);
    cudaGetSymbolAddress((void**)&p_zmid, g_zmid);
    cudaGetSymbolAddress((void**)&p_a1,   g_a1);
    cudaGetSymbolAddress((void**)&p_a2,   g_a2);
    cudaGetSymbolAddress((void**)&p_a3T,  g_a3T);
    cudaGetSymbolAddress((void**)&p_dk,   g_dknot);
    cudaGetSymbolAddress((void**)&p_dm,   g_dmid);

    k_logsig<<<128, 256>>>(x);
    k_lnorm <<<8192, 256>>>(sg, sb);
    k_spline<<<232, 128>>>();
    k_h0    <<<128, 256>>>(x, hW1, hb1, hW2, hb2);

    for (int n = 0; n < 63; n++){
        const float* dk = p_dk + (size_t)n*232*128;
        const float* dm = p_dm + (size_t)n*232*128;
        // eval 1: k1 = g(z, d_knot); zmid = z + 0.5h k1
        k_gemm<<<dim3(16,8), 256>>>(p_z, fW1, fb1, p_a1, 256, 1024, 0);
        k_ln  <<<128, 256>>>(p_a1, g1, be1, 1024);
        k_gemm<<<dim3(4,8), 256>>>(p_a1, fW2, fb2, p_a2, 1024, 256, 0);
        k_ln  <<<128, 256>>>(p_a2, g2, be2, 256);
        k_gemm<<<dim3(4,8), 256>>>(p_a2, fW3, fb3, p_a3T, 256, 256, 1);
        k_g   <<<256, 256>>>(fW4, fb4, dk, p_z, p_zmid, 0.5f*HSTEP);
        // eval 2: z = z + h * g(zmid, d_mid)
        k_gemm<<<dim3(16,8), 256>>>(p_zmid, fW1, fb1, p_a1, 256, 1024, 0);
        k_ln  <<<128, 256>>>(p_a1, g1, be1, 1024);
        k_gemm<<<dim3(4,8), 256>>>(p_a1, fW2, fb2, p_a2, 1024, 256, 0);
        k_ln  <<<128, 256>>>(p_a2, g2, be2, 256);
        k_gemm<<<dim3(4,8), 256>>>(p_a2, fW3, fb3, p_a3T, 256, 256, 1);
        k_g   <<<256, 256>>>(fW4, fb4, dm, p_z, p_z, HSTEP);
    }
    k_head<<<128, 256>>>(yW1, yb1, yW2, yb2, zW1, zb1, zW2, zb2, out);
}

// round 8
// speedup vs baseline: 2.0170x; 1.4247x over previous
#include <cuda_runtime.h>
#include <cuda_bf16.h>
#include <cstdint>

#define HSTEP (1.0f/63.0f)
// 9 chunks x 7 steps; C holds one chunk: 7*2*128 = 1792 rows
#define CH_STEPS 7
#define CH_ROWS  1792

// ---------------- scratch ----------------
static __device__ float g_lsraw[128*64*231];
static __device__ float g_y[128*64*232];
static __device__ float g_dknot[63*232*128];
static __device__ float g_dmid [63*232*128];
static __device__ float g_z[128*256];
static __device__ float g_zmid[128*256];
static __device__ float g_a1[128*1024];
static __device__ float g_a2[128*256];
// precompute path
static __device__ __nv_bfloat16 g_Asp[(size_t)16128*704];   // D split  [j][704]
static __device__ __nv_bfloat16 g_Bsp[(size_t)65536*704];   // fW4 split [n][704]
static __device__ float g_Dp [(size_t)16128*256];            // D fp32 padded
static __device__ float g_bt [(size_t)16128*256];            // bias term
static __device__ float g_fb4T[256*256];                     // fb4 transposed+padded
static __device__ float g_zero[256];                         // stays zero
static __device__ float g_C[(size_t)CH_ROWS*65536];          // 470 MB ring chunk

// ---------------- helpers ----------------
__device__ __forceinline__ float2 ffma2(float2 a, float2 b, float2 c){
    unsigned long long au, bu, cu, du;
    au = *reinterpret_cast<unsigned long long*>(&a);
    bu = *reinterpret_cast<unsigned long long*>(&b);
    cu = *reinterpret_cast<unsigned long long*>(&c);
    asm("fma.rn.f32x2 %0,%1,%2,%3;" : "=l"(du) : "l"(au), "l"(bu), "l"(cu));
    return *reinterpret_cast<float2*>(&du);
}

__device__ __forceinline__ uint32_t smem_u32(const void* p){
    uint32_t a;
    asm("{ .reg .u64 t; cvta.to.shared.u64 t, %1; cvt.u32.u64 %0, t; }"
        : "=r"(a) : "l"(p));
    return a;
}

__device__ __forceinline__ void ldsm4(uint32_t* r, uint32_t addr){
    asm volatile("ldmatrix.sync.aligned.m8n8.x4.shared.b16 {%0,%1,%2,%3}, [%4];"
        : "=r"(r[0]), "=r"(r[1]), "=r"(r[2]), "=r"(r[3]) : "r"(addr));
}

__device__ __forceinline__ void mma_bf16(float* c, const uint32_t* a, const uint32_t* b){
    asm volatile("mma.sync.aligned.m16n8k16.row.col.f32.bf16.bf16.f32 "
        "{%0,%1,%2,%3}, {%4,%5,%6,%7}, {%8,%9}, {%0,%1,%2,%3};"
        : "+f"(c[0]), "+f"(c[1]), "+f"(c[2]), "+f"(c[3])
        : "r"(a[0]), "r"(a[1]), "r"(a[2]), "r"(a[3]), "r"(b[0]), "r"(b[1]));
}

__device__ __forceinline__ void cpasync16(uint32_t dst, const void* src){
    asm volatile("cp.async.cg.shared.global [%0], [%1], 16;" :: "r"(dst), "l"(src));
}

__device__ __forceinline__ void block_reduce_sum2(float& s, float& q){
    __shared__ float sh[64];
    const unsigned m = 0xffffffffu;
    #pragma unroll
    for (int off = 16; off; off >>= 1){
        s += __shfl_down_sync(m, s, off);
        q += __shfl_down_sync(m, q, off);
    }
    int w = threadIdx.x >> 5, l = threadIdx.x & 31;
    if (l == 0){ sh[w] = s; sh[32+w] = q; }
    __syncthreads();
    if (threadIdx.x == 0){
        float ts = 0.f, tq = 0.f;
        int nw = blockDim.x >> 5;
        for (int i = 0; i < nw; i++){ ts += sh[i]; tq += sh[32+i]; }
        sh[0] = ts; sh[32] = tq;
    }
    __syncthreads();
    s = sh[0]; q = sh[32];
}

// ---- 1) depth-2 log-signature ----
__global__ void k_logsig(const float* __restrict__ x){
    int b = blockIdx.x;
    __shared__ float psh[64*21];
    for (int idx = threadIdx.x; idx < 64*21; idx += blockDim.x){
        int n = idx / 21, i = idx % 21;
        psh[idx] = (i == 0) ? (float)n * HSTEP : x[(b*64 + n)*20 + (i-1)];
    }
    __syncthreads();
    int ch = threadIdx.x;
    if (ch < 21){
        for (int n = 0; n < 64; n++)
            g_lsraw[((size_t)b*64 + n)*231 + ch] = psh[n*21 + ch];
    } else if (ch < 231){
        int pp = ch - 21, i = 0, rem = pp;
        while (rem >= 20 - i){ rem -= 20 - i; i++; }
        int j = i + 1 + rem;
        float acc = 0.f, pip = 0.f, pjp = 0.f;
        for (int n = 0; n < 64; n++){
            float pi = psh[n*21 + i], pj = psh[n*21 + j];
            acc += 0.5f*(pip*(pj - pjp) - (pi - pip)*pjp);
            g_lsraw[((size_t)b*64 + n)*231 + ch] = acc;
            pip = pi; pjp = pj;
        }
    }
}

// ---- 2) sig_norm LN + control y ----
__global__ void k_lnorm(const float* __restrict__ sg, const float* __restrict__ sb){
    int r = blockIdx.x, t = threadIdx.x;
    float v = (t < 231) ? g_lsraw[(size_t)r*231 + t] : 0.f;
    float s = v, q = v*v;
    block_reduce_sum2(s, q);
    float mean = s*(1.0f/231.0f);
    float var  = q*(1.0f/231.0f) - mean*mean;
    float rstd = rsqrtf(var + 1e-5f);
    if (t < 231) g_y[(size_t)r*232 + 1 + t] = (v - mean)*rstd*sg[t] + sb[t];
    if (t == 0)  g_y[(size_t)r*232] = (float)(r & 63) * HSTEP;
}

// ---- 3) natural cubic spline derivatives ----
__global__ void k_spline(){
    __shared__ float cpS[64], idS[64];
    int t = threadIdx.x;
    if (t == 0){
        double ad = (1.0/63.0)/6.0, bd = 2.0*(1.0/63.0)/3.0, cprev = 0.0;
        for (int i = 1; i <= 62; i++){
            double den = bd - ad*cprev, cp = ad/den;
            cpS[i] = (float)cp; idS[i] = (float)(1.0/den); cprev = cp;
        }
    }
    __syncthreads();
    int g = blockIdx.x*128 + t;
    int b = g / 232, c = g % 232;
    float yv[64], M[64];
    for (int n = 0; n < 64; n++) yv[n] = g_y[((size_t)b*64 + n)*232 + c];
    const float ad = HSTEP/6.0f;
    M[0] = 0.f; M[63] = 0.f;
    float prev = 0.f;
    for (int i = 1; i <= 62; i++){
        float rhs = (yv[i+1] - 2.f*yv[i] + yv[i-1]) * 63.0f;
        prev = (rhs - ad*prev) * idS[i];
        M[i] = prev;
    }
    for (int i = 61; i >= 1; i--) M[i] -= cpS[i]*M[i+1];
    for (int n = 0; n < 63; n++){
        float dy = (yv[n+1] - yv[n]) * 63.0f;
        size_t o = ((size_t)n*232 + c)*128 + b;
        g_dknot[o] = dy - (HSTEP/6.0f) *(2.f*M[n] + M[n+1]);
        g_dmid [o] = dy + (HSTEP/24.0f)*(M[n] - M[n+1]);
    }
}

// ---- pack kernels ----
__global__ void k_packD(){
    int j = blockIdx.x, c = threadIdx.x;
    int n = j >> 8, e = (j >> 7) & 1, b = j & 127;
    const float* src = e ? g_dmid : g_dknot;
    if (c < 232){
        float v = src[((size_t)n*232 + c)*128 + b];
        __nv_bfloat16 h = __float2bfloat16(v);
        float hf = __bfloat162float(h);
        __nv_bfloat16 l = __float2bfloat16(v - hf);
        g_Asp[(size_t)j*704 + c]       = h;
        g_Asp[(size_t)j*704 + 232 + c] = h;
        g_Asp[(size_t)j*704 + 464 + c] = l;
        g_Dp[(size_t)j*256 + c] = v;
    } else {
        if (c < 240) g_Asp[(size_t)j*704 + 696 + (c - 232)] = __float2bfloat16(0.f);
        g_Dp[(size_t)j*256 + c] = 0.f;
    }
}

__global__ void k_packW(const float* __restrict__ fW4){
    int nrow = blockIdx.x, c = threadIdx.x;
    if (c < 232){
        float v = fW4[(size_t)nrow*232 + c];
        __nv_bfloat16 h = __float2bfloat16(v);
        float hf = __bfloat162float(h);
        __nv_bfloat16 l = __float2bfloat16(v - hf);
        g_Bsp[(size_t)nrow*704 + c]       = h;
        g_Bsp[(size_t)nrow*704 + 232 + c] = l;
        g_Bsp[(size_t)nrow*704 + 464 + c] = h;
    } else if (c < 240){
        g_Bsp[(size_t)nrow*704 + 696 + (c - 232)] = __float2bfloat16(0.f);
    }
}

__global__ void k_packfbT(const float* __restrict__ fb4){
    int c = blockIdx.x, h = threadIdx.x;
    g_fb4T[c*256 + h] = (c < 232) ? fb4[(size_t)h*232 + c] : 0.f;
}

// ---- 4) initial hidden state ----
__global__ void k_h0(const float* __restrict__ x,  const float* __restrict__ hW1,
                     const float* __restrict__ hb1, const float* __restrict__ hW2,
                     const float* __restrict__ hb2){
    int b = blockIdx.x, t = threadIdx.x;
    __shared__ float x0[20];
    __shared__ float hid[256];
    if (t < 20) x0[t] = x[(size_t)b*64*20 + t];
    __syncthreads();
    float s = hb1[t];
    for (int d = 0; d < 20; d++) s = fmaf(x0[d], hW1[d*256 + t], s);
    hid[t] = fmaxf(s, 0.f);
    __syncthreads();
    float s2 = hb2[t];
    for (int k = 0; k < 256; k++) s2 = fmaf(hid[k], hW2[k*256 + t], s2);
    g_z[b*256 + t] = s2;
}

// ---- generic tiled GEMM (MLP stages 1-2 + bias-term precompute) ----
__global__ void __launch_bounds__(256) k_gemm(
    const float* __restrict__ in, const float* __restrict__ W,
    const float* __restrict__ bias, float* __restrict__ out,
    int K, int Nout)
{
    __shared__ float wsh[2048];
    __shared__ float ish[512];
    int n0 = blockIdx.x*64, b0 = blockIdx.y*16;
    int t = threadIdx.x, bi = t >> 4, ng = t & 15;
    float4 bia = *(const float4*)(bias + n0 + ng*4);
    float2 acc0 = make_float2(bia.x, bia.y);
    float2 acc1 = make_float2(bia.z, bia.w);
    for (int k0 = 0; k0 < K; k0 += 32){
        __syncthreads();
        #pragma unroll
        for (int j = 0; j < 8; j++){
            int e = t + j*256;
            wsh[e] = W[(size_t)(k0 + (e >> 6))*Nout + n0 + (e & 63)];
        }
        #pragma unroll
        for (int j = 0; j < 2; j++){
            int e = t + j*256;
            ish[e] = in[(size_t)(b0 + (e >> 5))*K + k0 + (e & 31)];
        }
        __syncthreads();
        #pragma unroll
        for (int kk = 0; kk < 32; kk++){
            float zv = ish[bi*32 + kk];
            float2 zz = make_float2(zv, zv);
            const float2* wp = (const float2*)(wsh + kk*64 + ng*4);
            acc0 = ffma2(zz, wp[0], acc0);
            acc1 = ffma2(zz, wp[1], acc1);
        }
    }
    float4 o = make_float4(acc0.x, acc0.y, acc1.x, acc1.y);
    *(float4*)(out + (size_t)(b0 + bi)*Nout + n0 + ng*4) = o;
}

// ---- LayerNorm + relu over width 1024, in place ----
__global__ void k_ln(float* __restrict__ buf, const float* __restrict__ gw,
                     const float* __restrict__ bw){
    int b = blockIdx.x, t = threadIdx.x;
    float v[4];
    float s = 0.f, q = 0.f;
    #pragma unroll
    for (int i = 0; i < 4; i++){
        v[i] = buf[(size_t)b*1024 + i*256 + t]; s += v[i]; q += v[i]*v[i];
    }
    block_reduce_sum2(s, q);
    float mean = s*(1.0f/1024.0f), var = q*(1.0f/1024.0f) - mean*mean;
    float rstd = rsqrtf(var + 1e-5f);
    #pragma unroll
    for (int i = 0; i < 4; i++){
        int idx = i*256 + t;
        buf[(size_t)b*1024 + idx] = fmaxf((v[i]-mean)*rstd*gw[idx] + bw[idx], 0.f);
    }
}

// ---- big GEMM on HMMA: C[1792 x 65536] = Asp_chunk @ Bspᵀ, K=704 ----
// block tile 128x128, 8 warps (2m x 4n), warp tile 64x32, 3-stage cp.async
__global__ void __launch_bounds__(256, 2) k_tc(
    const __nv_bfloat16* __restrict__ A, const __nv_bfloat16* __restrict__ Bm,
    float* __restrict__ C)
{
    extern __shared__ __align__(128) char dsm[];
    uint32_t base = (smem_u32(dsm) + 127u) & ~127u;
    int t = threadIdx.x, lane = t & 31, warp = t >> 5;
    int mw = warp & 1, nw = warp >> 1;
    size_t j0 = (size_t)blockIdx.x * 128, n0 = (size_t)blockIdx.y * 128;
    const char* Ab = (const char*)A  + j0*1408;
    const char* Bb = (const char*)Bm + n0*1408;

    auto stg = [&](int ck, int s){
        uint32_t sb = base + s*32768u;
        #pragma unroll
        for (int i = 0; i < 4; i++){
            int e = t*4 + i;
            int row = e >> 3, q = e & 7;
            uint32_t d = sb + row*128 + ((q ^ (row & 7)) << 4);
            cpasync16(d, Ab + (size_t)row*1408 + ck*128 + q*16);
        }
        #pragma unroll
        for (int i = 0; i < 4; i++){
            int e = t*4 + i;
            int row = e >> 3, q = e & 7;
            uint32_t d = sb + 16384u + row*128 + ((q ^ (row & 7)) << 4);
            cpasync16(d, Bb + (size_t)row*1408 + ck*128 + q*16);
        }
        asm volatile("cp.async.commit_group;" ::: "memory");
    };

    float acc[4][4][4];
    #pragma unroll
    for (int mi = 0; mi < 4; mi++)
        #pragma unroll
        for (int ni = 0; ni < 4; ni++)
            #pragma unroll
            for (int r = 0; r < 4; r++) acc[mi][ni][r] = 0.f;

    stg(0, 0); stg(1, 1); stg(2, 2);

    for (int ck = 0; ck < 11; ck++){
        if (ck < 8) asm volatile("cp.async.wait_group 2;" ::: "memory");
        else        asm volatile("cp.async.wait_group 0;" ::: "memory");
        __syncthreads();
        uint32_t sA = base + (uint32_t)(ck % 3)*32768u;
        uint32_t sB = sA + 16384u;
        #pragma unroll
        for (int kk = 0; kk < 4; kk++){
            uint32_t afr[4][4], bfr[2][4];
            #pragma unroll
            for (int mi = 0; mi < 4; mi++){
                int row = mw*64 + mi*16 + (lane & 15);
                int q = kk*2 + (lane >> 4);
                ldsm4(afr[mi], sA + row*128 + ((q ^ (row & 7)) << 4));
            }
            #pragma unroll
            for (int nj = 0; nj < 2; nj++){
                int row = nw*32 + nj*16 + (lane & 7) + ((lane >> 4) & 1)*8;
                int q = kk*2 + ((lane >> 3) & 1);
                ldsm4(bfr[nj], sB + row*128 + ((q ^ (row & 7)) << 4));
            }
            #pragma unroll
            for (int mi = 0; mi < 4; mi++)
                #pragma unroll
                for (int ni = 0; ni < 4; ni++)
                    mma_bf16(acc[mi][ni], afr[mi], &bfr[ni >> 1][(ni & 1)*2]);
        }
        __syncthreads();
        if (ck + 3 < 11) stg(ck + 3, ck % 3);
    }

    #pragma unroll
    for (int mi = 0; mi < 4; mi++){
        size_t r0 = j0 + mw*64 + mi*16 + (lane >> 2);
        float* row0 = C + r0*65536 + n0 + nw*32 + (lane & 3)*2;
        float* row1 = row0 + (size_t)8*65536;
        #pragma unroll
        for (int ni = 0; ni < 4; ni++){
            *(float2*)(row0 + ni*8) = make_float2(acc[mi][ni][0], acc[mi][ni][1]);
            *(float2*)(row1 + ni*8) = make_float2(acc[mi][ni][2], acc[mi][ni][3]);
        }
    }
}

// ---- fused: LN(a2)+relu -> a3 = relu(@fW3+fb3) -> g = bt + a3·C -> z update ----
// jl: local C row base (within chunk); jg: global bt row base
__global__ void k_fuse3(const float* __restrict__ fW3, const float* __restrict__ fb3,
                        const float* __restrict__ g2,  const float* __restrict__ be2,
                        const float* __restrict__ C,   const float* __restrict__ bt,
                        const float* __restrict__ a2raw,
                        const float* __restrict__ zbase, float* __restrict__ zout,
                        int jl, int jg, float coef)
{
    __shared__ float ash[256];
    __shared__ float a3sh[256];
    int b = blockIdx.x, t = threadIdx.x;
    float v = a2raw[(size_t)b*256 + t];
    float s = v, q = v*v;
    block_reduce_sum2(s, q);
    float mean = s*(1.0f/256.0f), var = q*(1.0f/256.0f) - mean*mean;
    float rstd = rsqrtf(var + 1e-5f);
    ash[t] = fmaxf((v - mean)*rstd*g2[t] + be2[t], 0.f);
    __syncthreads();
    float acc = fb3[t];
    #pragma unroll 8
    for (int k = 0; k < 256; k++)
        acc = fmaf(ash[k], __ldg(fW3 + (size_t)k*256 + t), acc);
    a3sh[t] = fmaxf(acc, 0.f);
    __syncthreads();
    const float* Crow = C + (size_t)(jl + b)*65536 + t;
    float g = bt[(size_t)(jg + b)*256 + t];
    #pragma unroll 8
    for (int k = 0; k < 256; k++)
        g = fmaf(a3sh[k], __ldg(Crow + (size_t)k*256), g);
    zout[b*256 + t] = zbase[b*256 + t] + coef*g;
}

// ---- output heads ----
__global__ void k_head(const float* __restrict__ yW1, const float* __restrict__ yb1,
                       const float* __restrict__ yW2, const float* __restrict__ yb2,
                       const float* __restrict__ zW1, const float* __restrict__ zb1,
                       const float* __restrict__ zW2, const float* __restrict__ zb2,
                       float* __restrict__ out){
    int b = blockIdx.x, t = threadIdx.x;
    __shared__ float hsh[256], t1[128], t2[256];
    hsh[t] = g_z[b*256 + t];
    __syncthreads();
    float s = zb1[t];
    for (int k = 0; k < 256; k++) s = fmaf(hsh[k], zW1[k*256 + t], s);
    t2[t] = fmaxf(s, 0.f);
    if (t < 128){
        float s1 = yb1[t];
        for (int k = 0; k < 256; k++) s1 = fmaf(hsh[k], yW1[k*128 + t], s1);
        t1[t] = fmaxf(s1, 0.f);
    }
    __syncthreads();
    if (t == 0){
        float y = yb2[0];
        for (int j = 0; j < 128; j++) y = fmaf(t1[j], yW2[j], y);
        out[b] = y;
    }
    if (t < 20){
        float zz = zb2[t];
        for (int k = 0; k < 256; k++) zz = fmaf(t2[k], zW2[k*20 + t], zz);
        out[128 + b*20 + t] = zz;
    }
    out[128 + 2560 + b*256 + t] = hsh[t];
}

extern "C" void kernel_launch(void* const* d_in, const int* in_sizes, int n_in,
                              void* d_out, int out_size){
    const float* x  =(const float*)d_in[0];
    const float* hW1=(const float*)d_in[1]; const float* hb1=(const float*)d_in[2];
    const float* hW2=(const float*)d_in[3]; const float* hb2=(const float*)d_in[4];
    const float* fW1=(const float*)d_in[5]; const float* fb1=(const float*)d_in[6];
    const float* g1 =(const float*)d_in[7]; const float* be1=(const float*)d_in[8];
    const float* fW2=(const float*)d_in[9]; const float* fb2=(const float*)d_in[10];
    const float* g2 =(const float*)d_in[11]; const float* be2=(const float*)d_in[12];
    const float* fW3=(const float*)d_in[13]; const float* fb3=(const float*)d_in[14];
    const float* fW4=(const float*)d_in[15]; const float* fb4=(const float*)d_in[16];
    const float* yW1=(const float*)d_in[17]; const float* yb1=(const float*)d_in[18];
    const float* yW2=(const float*)d_in[19]; const float* yb2=(const float*)d_in[20];
    const float* zW1=(const float*)d_in[21]; const float* zb1=(const float*)d_in[22];
    const float* zW2=(const float*)d_in[23]; const float* zb2=(const float*)d_in[24];
    const float* sg =(const float*)d_in[25]; const float* sb =(const float*)d_in[26];
    float* out = (float*)d_out;

    float *p_z, *p_zmid, *p_a1, *p_a2, *p_Dp, *p_bt, *p_fbT, *p_zero, *p_C;
    __nv_bfloat16 *p_A, *p_B;
    cudaGetSymbolAddress((void**)&p_z,    g_z);
    cudaGetSymbolAddress((void**)&p_zmid, g_zmid);
    cudaGetSymbolAddress((void**)&p_a1,   g_a1);
    cudaGetSymbolAddress((void**)&p_a2,   g_a2);
    cudaGetSymbolAddress((void**)&p_Dp,   g_Dp);
    cudaGetSymbolAddress((void**)&p_bt,   g_bt);
    cudaGetSymbolAddress((void**)&p_fbT,  g_fb4T);
    cudaGetSymbolAddress((void**)&p_zero, g_zero);
    cudaGetSymbolAddress((void**)&p_C,    g_C);
    cudaGetSymbolAddress((void**)&p_A,    g_Asp);
    cudaGetSymbolAddress((void**)&p_B,    g_Bsp);

    const int DSM = 98432;  // 3 stages x 32KB + alignment
    cudaFuncSetAttribute(k_tc, cudaFuncAttributeMaxDynamicSharedMemorySize, DSM);

    // prep
    k_packW  <<<65536, 256>>>(fW4);
    k_packfbT<<<256, 256>>>(fb4);
    k_logsig <<<128, 256>>>(x);
    k_lnorm  <<<8192, 256>>>(sg, sb);
    k_spline <<<232, 128>>>();
    k_packD  <<<16128, 256>>>();
    // bias term: bt = Dp(16128x256) @ fb4T(256x256)
    k_gemm   <<<dim3(4,1008), 256>>>(p_Dp, p_fbT, p_zero, p_bt, 256, 256);
    k_h0     <<<128, 256>>>(x, hW1, hb1, hW2, hb2);

    for (int chunk = 0; chunk < 9; chunk++){
        // produce C for this chunk of 7 steps (1792 rows)
        k_tc<<<dim3(CH_ROWS/128, 512), 256, DSM>>>(
            p_A + (size_t)chunk*CH_ROWS*704, p_B, p_C);
        for (int s = 0; s < CH_STEPS; s++){
            int n = chunk*CH_STEPS + s;
            int jg0 = (2*n)*128,     jl0 = (2*s)*128;
            int jg1 = (2*n + 1)*128, jl1 = (2*s + 1)*128;
            // eval 1: k1 = g(z, d_knot); zmid = z + 0.5h k1
            k_gemm <<<dim3(16,8), 256>>>(p_z, fW1, fb1, p_a1, 256, 1024);
            k_ln   <<<128, 256>>>(p_a1, g1, be1);
            k_gemm <<<dim3(4,8), 256>>>(p_a1, fW2, fb2, p_a2, 1024, 256);
            k_fuse3<<<128, 256>>>(fW3, fb3, g2, be2, p_C, p_bt, p_a2,
                                  p_z, p_zmid, jl0, jg0, 0.5f*HSTEP);
            // eval 2: z = z + h * g(zmid, d_mid)
            k_gemm <<<dim3(16,8), 256>>>(p_zmid, fW1, fb1, p_a1, 256, 1024);
            k_ln   <<<128, 256>>>(p_a1, g1, be1);
            k_gemm <<<dim3(4,8), 256>>>(p_a1, fW2, fb2, p_a2, 1024, 256);
            k_fuse3<<<128, 256>>>(fW3, fb3, g2, be2, p_C, p_bt, p_a2,
                                  p_z, p_z, jl1, jg1, HSTEP);
        }
    }
    k_head<<<128, 256>>>(yW1, yb1, yW2, yb2, zW1, zb1, zW2, zb2, out);
}

// round 9
// speedup vs baseline: 2.0439x; 1.0133x over previous
#include <cuda_runtime.h>
#include <cuda_bf16.h>
#include <cstdint>

#define HSTEP (1.0f/63.0f)
#define CH_STEPS 7
#define CH_ROWS  1792

// ---------------- scratch ----------------
static __device__ float g_lsraw[128*64*231];
static __device__ float g_y[128*64*232];
static __device__ float g_dknot[63*232*128];
static __device__ float g_dmid [63*232*128];
static __device__ float g_z[128*256];
static __device__ float g_zmid[128*256];
static __device__ float g_a1[128*1024];
// precompute path
static __device__ __nv_bfloat16 g_Asp[(size_t)16128*704];
static __device__ __nv_bfloat16 g_Bsp[(size_t)65536*704];
static __device__ float g_Dp [(size_t)16128*256];
static __device__ float g_bt [(size_t)16128*256];
static __device__ float g_fb4T[256*256];
static __device__ float g_zero[256];
static __device__ float g_C[(size_t)CH_ROWS*65536];   // 470 MB ring chunk

// ---------------- helpers ----------------
__device__ __forceinline__ float2 ffma2(float2 a, float2 b, float2 c){
    unsigned long long au, bu, cu, du;
    au = *reinterpret_cast<unsigned long long*>(&a);
    bu = *reinterpret_cast<unsigned long long*>(&b);
    cu = *reinterpret_cast<unsigned long long*>(&c);
    asm("fma.rn.f32x2 %0,%1,%2,%3;" : "=l"(du) : "l"(au), "l"(bu), "l"(cu));
    return *reinterpret_cast<float2*>(&du);
}

__device__ __forceinline__ uint32_t smem_u32(const void* p){
    uint32_t a;
    asm("{ .reg .u64 t; cvta.to.shared.u64 t, %1; cvt.u32.u64 %0, t; }"
        : "=r"(a) : "l"(p));
    return a;
}

__device__ __forceinline__ void ldsm4(uint32_t* r, uint32_t addr){
    asm volatile("ldmatrix.sync.aligned.m8n8.x4.shared.b16 {%0,%1,%2,%3}, [%4];"
        : "=r"(r[0]), "=r"(r[1]), "=r"(r[2]), "=r"(r[3]) : "r"(addr));
}

__device__ __forceinline__ void mma_bf16(float* c, const uint32_t* a, const uint32_t* b){
    asm volatile("mma.sync.aligned.m16n8k16.row.col.f32.bf16.bf16.f32 "
        "{%0,%1,%2,%3}, {%4,%5,%6,%7}, {%8,%9}, {%0,%1,%2,%3};"
        : "+f"(c[0]), "+f"(c[1]), "+f"(c[2]), "+f"(c[3])
        : "r"(a[0]), "r"(a[1]), "r"(a[2]), "r"(a[3]), "r"(b[0]), "r"(b[1]));
}

__device__ __forceinline__ void cpasync16(uint32_t dst, const void* src){
    asm volatile("cp.async.cg.shared.global [%0], [%1], 16;" :: "r"(dst), "l"(src));
}

__device__ __forceinline__ void block_reduce_sum2(float& s, float& q){
    __shared__ float sh[64];
    const unsigned m = 0xffffffffu;
    #pragma unroll
    for (int off = 16; off; off >>= 1){
        s += __shfl_down_sync(m, s, off);
        q += __shfl_down_sync(m, q, off);
    }
    int w = threadIdx.x >> 5, l = threadIdx.x & 31;
    if (l == 0){ sh[w] = s; sh[32+w] = q; }
    __syncthreads();
    if (threadIdx.x == 0){
        float ts = 0.f, tq = 0.f;
        int nw = blockDim.x >> 5;
        for (int i = 0; i < nw; i++){ ts += sh[i]; tq += sh[32+i]; }
        sh[0] = ts; sh[32] = tq;
    }
    __syncthreads();
    s = sh[0]; q = sh[32];
}

// ---- 1) depth-2 log-signature ----
__global__ void k_logsig(const float* __restrict__ x){
    int b = blockIdx.x;
    __shared__ float psh[64*21];
    for (int idx = threadIdx.x; idx < 64*21; idx += blockDim.x){
        int n = idx / 21, i = idx % 21;
        psh[idx] = (i == 0) ? (float)n * HSTEP : x[(b*64 + n)*20 + (i-1)];
    }
    __syncthreads();
    int ch = threadIdx.x;
    if (ch < 21){
        for (int n = 0; n < 64; n++)
            g_lsraw[((size_t)b*64 + n)*231 + ch] = psh[n*21 + ch];
    } else if (ch < 231){
        int pp = ch - 21, i = 0, rem = pp;
        while (rem >= 20 - i){ rem -= 20 - i; i++; }
        int j = i + 1 + rem;
        float acc = 0.f, pip = 0.f, pjp = 0.f;
        for (int n = 0; n < 64; n++){
            float pi = psh[n*21 + i], pj = psh[n*21 + j];
            acc += 0.5f*(pip*(pj - pjp) - (pi - pip)*pjp);
            g_lsraw[((size_t)b*64 + n)*231 + ch] = acc;
            pip = pi; pjp = pj;
        }
    }
}

// ---- 2) sig_norm LN + control y ----
__global__ void k_lnorm(const float* __restrict__ sg, const float* __restrict__ sb){
    int r = blockIdx.x, t = threadIdx.x;
    float v = (t < 231) ? g_lsraw[(size_t)r*231 + t] : 0.f;
    float s = v, q = v*v;
    block_reduce_sum2(s, q);
    float mean = s*(1.0f/231.0f);
    float var  = q*(1.0f/231.0f) - mean*mean;
    float rstd = rsqrtf(var + 1e-5f);
    if (t < 231) g_y[(size_t)r*232 + 1 + t] = (v - mean)*rstd*sg[t] + sb[t];
    if (t == 0)  g_y[(size_t)r*232] = (float)(r & 63) * HSTEP;
}

// ---- 3) natural cubic spline derivatives ----
__global__ void k_spline(){
    __shared__ float cpS[64], idS[64];
    int t = threadIdx.x;
    if (t == 0){
        double ad = (1.0/63.0)/6.0, bd = 2.0*(1.0/63.0)/3.0, cprev = 0.0;
        for (int i = 1; i <= 62; i++){
            double den = bd - ad*cprev, cp = ad/den;
            cpS[i] = (float)cp; idS[i] = (float)(1.0/den); cprev = cp;
        }
    }
    __syncthreads();
    int g = blockIdx.x*128 + t;
    int b = g / 232, c = g % 232;
    float yv[64], M[64];
    for (int n = 0; n < 64; n++) yv[n] = g_y[((size_t)b*64 + n)*232 + c];
    const float ad = HSTEP/6.0f;
    M[0] = 0.f; M[63] = 0.f;
    float prev = 0.f;
    for (int i = 1; i <= 62; i++){
        float rhs = (yv[i+1] - 2.f*yv[i] + yv[i-1]) * 63.0f;
        prev = (rhs - ad*prev) * idS[i];
        M[i] = prev;
    }
    for (int i = 61; i >= 1; i--) M[i] -= cpS[i]*M[i+1];
    for (int n = 0; n < 63; n++){
        float dy = (yv[n+1] - yv[n]) * 63.0f;
        size_t o = ((size_t)n*232 + c)*128 + b;
        g_dknot[o] = dy - (HSTEP/6.0f) *(2.f*M[n] + M[n+1]);
        g_dmid [o] = dy + (HSTEP/24.0f)*(M[n] - M[n+1]);
    }
}

// ---- pack kernels ----
__global__ void k_packD(){
    int j = blockIdx.x, c = threadIdx.x;
    int n = j >> 8, e = (j >> 7) & 1, b = j & 127;
    const float* src = e ? g_dmid : g_dknot;
    if (c < 232){
        float v = src[((size_t)n*232 + c)*128 + b];
        __nv_bfloat16 h = __float2bfloat16(v);
        float hf = __bfloat162float(h);
        __nv_bfloat16 l = __float2bfloat16(v - hf);
        g_Asp[(size_t)j*704 + c]       = h;
        g_Asp[(size_t)j*704 + 232 + c] = h;
        g_Asp[(size_t)j*704 + 464 + c] = l;
        g_Dp[(size_t)j*256 + c] = v;
    } else {
        if (c < 240) g_Asp[(size_t)j*704 + 696 + (c - 232)] = __float2bfloat16(0.f);
        g_Dp[(size_t)j*256 + c] = 0.f;
    }
}

__global__ void k_packW(const float* __restrict__ fW4){
    int nrow = blockIdx.x, c = threadIdx.x;
    if (c < 232){
        float v = fW4[(size_t)nrow*232 + c];
        __nv_bfloat16 h = __float2bfloat16(v);
        float hf = __bfloat162float(h);
        __nv_bfloat16 l = __float2bfloat16(v - hf);
        g_Bsp[(size_t)nrow*704 + c]       = h;
        g_Bsp[(size_t)nrow*704 + 232 + c] = l;
        g_Bsp[(size_t)nrow*704 + 464 + c] = h;
    } else if (c < 240){
        g_Bsp[(size_t)nrow*704 + 696 + (c - 232)] = __float2bfloat16(0.f);
    }
}

__global__ void k_packfbT(const float* __restrict__ fb4){
    int c = blockIdx.x, h = threadIdx.x;
    g_fb4T[c*256 + h] = (c < 232) ? fb4[(size_t)h*232 + c] : 0.f;
}

// ---- 4) initial hidden state ----
__global__ void k_h0(const float* __restrict__ x,  const float* __restrict__ hW1,
                     const float* __restrict__ hb1, const float* __restrict__ hW2,
                     const float* __restrict__ hb2){
    int b = blockIdx.x, t = threadIdx.x;
    __shared__ float x0[20];
    __shared__ float hid[256];
    if (t < 20) x0[t] = x[(size_t)b*64*20 + t];
    __syncthreads();
    float s = hb1[t];
    for (int d = 0; d < 20; d++) s = fmaf(x0[d], hW1[d*256 + t], s);
    hid[t] = fmaxf(s, 0.f);
    __syncthreads();
    float s2 = hb2[t];
    for (int k = 0; k < 256; k++) s2 = fmaf(hid[k], hW2[k*256 + t], s2);
    g_z[b*256 + t] = s2;
}

// ---- generic tiled GEMM (bias-term precompute only) ----
__global__ void __launch_bounds__(256) k_gemm(
    const float* __restrict__ in, const float* __restrict__ W,
    const float* __restrict__ bias, float* __restrict__ out,
    int K, int Nout)
{
    __shared__ float wsh[2048];
    __shared__ float ish[512];
    int n0 = blockIdx.x*64, b0 = blockIdx.y*16;
    int t = threadIdx.x, bi = t >> 4, ng = t & 15;
    float4 bia = *(const float4*)(bias + n0 + ng*4);
    float2 acc0 = make_float2(bia.x, bia.y);
    float2 acc1 = make_float2(bia.z, bia.w);
    for (int k0 = 0; k0 < K; k0 += 32){
        __syncthreads();
        #pragma unroll
        for (int j = 0; j < 8; j++){
            int e = t + j*256;
            wsh[e] = W[(size_t)(k0 + (e >> 6))*Nout + n0 + (e & 63)];
        }
        #pragma unroll
        for (int j = 0; j < 2; j++){
            int e = t + j*256;
            ish[e] = in[(size_t)(b0 + (e >> 5))*K + k0 + (e & 31)];
        }
        __syncthreads();
        #pragma unroll
        for (int kk = 0; kk < 32; kk++){
            float zv = ish[bi*32 + kk];
            float2 zz = make_float2(zv, zv);
            const float2* wp = (const float2*)(wsh + kk*64 + ng*4);
            acc0 = ffma2(zz, wp[0], acc0);
            acc1 = ffma2(zz, wp[1], acc1);
        }
    }
    float4 o = make_float4(acc0.x, acc0.y, acc1.x, acc1.y);
    *(float4*)(out + (size_t)(b0 + bi)*Nout + n0 + ng*4) = o;
}

// ---- big GEMM on HMMA: C[1792 x 65536] = Asp_chunk @ Bspᵀ, K=704 ----
__global__ void __launch_bounds__(256, 2) k_tc(
    const __nv_bfloat16* __restrict__ A, const __nv_bfloat16* __restrict__ Bm,
    float* __restrict__ C)
{
    extern __shared__ __align__(128) char dsm[];
    uint32_t base = (smem_u32(dsm) + 127u) & ~127u;
    int t = threadIdx.x, lane = t & 31, warp = t >> 5;
    int mw = warp & 1, nw = warp >> 1;
    size_t j0 = (size_t)blockIdx.x * 128, n0 = (size_t)blockIdx.y * 128;
    const char* Ab = (const char*)A  + j0*1408;
    const char* Bb = (const char*)Bm + n0*1408;

    auto stg = [&](int ck, int s){
        uint32_t sb = base + s*32768u;
        #pragma unroll
        for (int i = 0; i < 4; i++){
            int e = t*4 + i;
            int row = e >> 3, q = e & 7;
            uint32_t d = sb + row*128 + ((q ^ (row & 7)) << 4);
            cpasync16(d, Ab + (size_t)row*1408 + ck*128 + q*16);
        }
        #pragma unroll
        for (int i = 0; i < 4; i++){
            int e = t*4 + i;
            int row = e >> 3, q = e & 7;
            uint32_t d = sb + 16384u + row*128 + ((q ^ (row & 7)) << 4);
            cpasync16(d, Bb + (size_t)row*1408 + ck*128 + q*16);
        }
        asm volatile("cp.async.commit_group;" ::: "memory");
    };

    float acc[4][4][4];
    #pragma unroll
    for (int mi = 0; mi < 4; mi++)
        #pragma unroll
        for (int ni = 0; ni < 4; ni++)
            #pragma unroll
            for (int r = 0; r < 4; r++) acc[mi][ni][r] = 0.f;

    stg(0, 0); stg(1, 1); stg(2, 2);

    for (int ck = 0; ck < 11; ck++){
        if (ck < 8) asm volatile("cp.async.wait_group 2;" ::: "memory");
        else        asm volatile("cp.async.wait_group 0;" ::: "memory");
        __syncthreads();
        uint32_t sA = base + (uint32_t)(ck % 3)*32768u;
        uint32_t sB = sA + 16384u;
        #pragma unroll
        for (int kk = 0; kk < 4; kk++){
            uint32_t afr[4][4], bfr[2][4];
            #pragma unroll
            for (int mi = 0; mi < 4; mi++){
                int row = mw*64 + mi*16 + (lane & 15);
                int q = kk*2 + (lane >> 4);
                ldsm4(afr[mi], sA + row*128 + ((q ^ (row & 7)) << 4));
            }
            #pragma unroll
            for (int nj = 0; nj < 2; nj++){
                int row = nw*32 + nj*16 + (lane & 7) + ((lane >> 4) & 1)*8;
                int q = kk*2 + ((lane >> 3) & 1);
                ldsm4(bfr[nj], sB + row*128 + ((q ^ (row & 7)) << 4));
            }
            #pragma unroll
            for (int mi = 0; mi < 4; mi++)
                #pragma unroll
                for (int ni = 0; ni < 4; ni++)
                    mma_bf16(acc[mi][ni], afr[mi], &bfr[ni >> 1][(ni & 1)*2]);
        }
        __syncthreads();
        if (ck + 3 < 11) stg(ck + 3, ck % 3);
    }

    #pragma unroll
    for (int mi = 0; mi < 4; mi++){
        size_t r0 = j0 + mw*64 + mi*16 + (lane >> 2);
        float* row0 = C + r0*65536 + n0 + nw*32 + (lane & 3)*2;
        float* row1 = row0 + (size_t)8*65536;
        #pragma unroll
        for (int ni = 0; ni < 4; ni++){
            *(float2*)(row0 + ni*8) = make_float2(acc[mi][ni][0], acc[mi][ni][1]);
            *(float2*)(row1 + ni*8) = make_float2(acc[mi][ni][2], acc[mi][ni][3]);
        }
    }
}

// ---- scan fused kernel 1: a1 = relu(LN(z @ fW1 + fb1)) ----
// block per batch; thread computes outputs 4t..4t+3
__global__ void __launch_bounds__(256) k_f1(
    const float* __restrict__ fW1, const float* __restrict__ fb1,
    const float* __restrict__ g1,  const float* __restrict__ be1,
    const float* __restrict__ zin, float* __restrict__ a1out)
{
    int b = blockIdx.x, t = threadIdx.x;
    __shared__ float zsh[256];
    zsh[t] = zin[b*256 + t];
    __syncthreads();
    float4 bv = __ldg((const float4*)fb1 + t);
    float2 acc0 = make_float2(bv.x, bv.y);
    float2 acc1 = make_float2(bv.z, bv.w);
    #pragma unroll 4
    for (int k = 0; k < 256; k++){
        float zv = zsh[k];
        float2 zz = make_float2(zv, zv);
        float4 w = __ldg((const float4*)(fW1 + (size_t)k*1024) + t);
        acc0 = ffma2(zz, make_float2(w.x, w.y), acc0);
        acc1 = ffma2(zz, make_float2(w.z, w.w), acc1);
    }
    float s = acc0.x + acc0.y + acc1.x + acc1.y;
    float q = acc0.x*acc0.x + acc0.y*acc0.y + acc1.x*acc1.x + acc1.y*acc1.y;
    block_reduce_sum2(s, q);
    float mean = s*(1.0f/1024.0f), var = q*(1.0f/1024.0f) - mean*mean;
    float rstd = rsqrtf(var + 1e-5f);
    float4 gg = __ldg((const float4*)g1 + t);
    float4 bb = __ldg((const float4*)be1 + t);
    float4 o;
    o.x = fmaxf((acc0.x - mean)*rstd*gg.x + bb.x, 0.f);
    o.y = fmaxf((acc0.y - mean)*rstd*gg.y + bb.y, 0.f);
    o.z = fmaxf((acc1.x - mean)*rstd*gg.z + bb.z, 0.f);
    o.w = fmaxf((acc1.y - mean)*rstd*gg.w + bb.w, 0.f);
    ((float4*)(a1out + (size_t)b*1024))[t] = o;
}

// ---- scan fused kernel 2: a2=relu(LN(a1@fW2+fb2)); a3=relu(a2@fW3+fb3);
//      g = bt + a3·C ; zout = zbase + coef*g ----
// block per batch. Split-k over fW2: half = t>>7 handles 512 k for outputs (2p,2p+1).
__global__ void __launch_bounds__(256) k_f2(
    const float* __restrict__ fW2, const float* __restrict__ fb2,
    const float* __restrict__ g2,  const float* __restrict__ be2,
    const float* __restrict__ fW3, const float* __restrict__ fb3,
    const float* __restrict__ C,   const float* __restrict__ bt,
    const float* __restrict__ a1,
    const float* __restrict__ zbase, float* __restrict__ zout,
    int jl, int jg, float coef)
{
    __shared__ __align__(16) float ash[1024];
    __shared__ float2 red[256];
    __shared__ float a2sh[256];
    __shared__ float a3sh[256];
    int b = blockIdx.x, t = threadIdx.x;
    ((float4*)ash)[t] = ((const float4*)(a1 + (size_t)b*1024))[t];
    __syncthreads();
    int half = t >> 7, p = t & 127;
    float2 acc = make_float2(0.f, 0.f);
    const float* wb = fW2 + (size_t)half*512*256 + 2*p;
    const float* ab = ash + half*512;
    #pragma unroll 8
    for (int k = 0; k < 512; k++){
        float av = ab[k];
        float2 w = __ldg((const float2*)(wb + (size_t)k*256));
        acc = ffma2(make_float2(av, av), w, acc);
    }
    red[t] = acc;
    __syncthreads();
    float s = 0.f, q = 0.f;
    float2 tot = make_float2(0.f, 0.f);
    if (t < 128){
        float2 lo = red[t], hi = red[t + 128];
        float2 bv = __ldg((const float2*)fb2 + t);
        tot = make_float2(lo.x + hi.x + bv.x, lo.y + hi.y + bv.y);
        s = tot.x + tot.y; q = tot.x*tot.x + tot.y*tot.y;
    }
    block_reduce_sum2(s, q);
    float mean = s*(1.0f/256.0f), var = q*(1.0f/256.0f) - mean*mean;
    float rstd = rsqrtf(var + 1e-5f);
    if (t < 128){
        float2 gg = __ldg((const float2*)g2 + t);
        float2 bb = __ldg((const float2*)be2 + t);
        a2sh[2*t]   = fmaxf((tot.x - mean)*rstd*gg.x + bb.x, 0.f);
        a2sh[2*t+1] = fmaxf((tot.y - mean)*rstd*gg.y + bb.y, 0.f);
    }
    __syncthreads();
    // a3 = relu(a2 @ fW3 + fb3)
    float acc3 = __ldg(fb3 + t);
    #pragma unroll 8
    for (int k = 0; k < 256; k++)
        acc3 = fmaf(a2sh[k], __ldg(fW3 + (size_t)k*256 + t), acc3);
    a3sh[t] = fmaxf(acc3, 0.f);
    __syncthreads();
    // g = bt + a3 · C rows
    const float* Crow = C + (size_t)(jl + b)*65536 + t;
    float g = __ldg(bt + (size_t)(jg + b)*256 + t);
    #pragma unroll 8
    for (int k = 0; k < 256; k++)
        g = fmaf(a3sh[k], __ldg(Crow + (size_t)k*256), g);
    zout[b*256 + t] = zbase[b*256 + t] + coef*g;
}

// ---- output heads ----
__global__ void k_head(const float* __restrict__ yW1, const float* __restrict__ yb1,
                       const float* __restrict__ yW2, const float* __restrict__ yb2,
                       const float* __restrict__ zW1, const float* __restrict__ zb1,
                       const float* __restrict__ zW2, const float* __restrict__ zb2,
                       float* __restrict__ out){
    int b = blockIdx.x, t = threadIdx.x;
    __shared__ float hsh[256], t1[128], t2[256];
    hsh[t] = g_z[b*256 + t];
    __syncthreads();
    float s = zb1[t];
    for (int k = 0; k < 256; k++) s = fmaf(hsh[k], zW1[k*256 + t], s);
    t2[t] = fmaxf(s, 0.f);
    if (t < 128){
        float s1 = yb1[t];
        for (int k = 0; k < 256; k++) s1 = fmaf(hsh[k], yW1[k*128 + t], s1);
        t1[t] = fmaxf(s1, 0.f);
    }
    __syncthreads();
    if (t == 0){
        float y = yb2[0];
        for (int j = 0; j < 128; j++) y = fmaf(t1[j], yW2[j], y);
        out[b] = y;
    }
    if (t < 20){
        float zz = zb2[t];
        for (int k = 0; k < 256; k++) zz = fmaf(t2[k], zW2[k*20 + t], zz);
        out[128 + b*20 + t] = zz;
    }
    out[128 + 2560 + b*256 + t] = hsh[t];
}

extern "C" void kernel_launch(void* const* d_in, const int* in_sizes, int n_in,
                              void* d_out, int out_size){
    const float* x  =(const float*)d_in[0];
    const float* hW1=(const float*)d_in[1]; const float* hb1=(const float*)d_in[2];
    const float* hW2=(const float*)d_in[3]; const float* hb2=(const float*)d_in[4];
    const float* fW1=(const float*)d_in[5]; const float* fb1=(const float*)d_in[6];
    const float* g1 =(const float*)d_in[7]; const float* be1=(const float*)d_in[8];
    const float* fW2=(const float*)d_in[9]; const float* fb2=(const float*)d_in[10];
    const float* g2 =(const float*)d_in[11]; const float* be2=(const float*)d_in[12];
    const float* fW3=(const float*)d_in[13]; const float* fb3=(const float*)d_in[14];
    const float* fW4=(const float*)d_in[15]; const float* fb4=(const float*)d_in[16];
    const float* yW1=(const float*)d_in[17]; const float* yb1=(const float*)d_in[18];
    const float* yW2=(const float*)d_in[19]; const float* yb2=(const float*)d_in[20];
    const float* zW1=(const float*)d_in[21]; const float* zb1=(const float*)d_in[22];
    const float* zW2=(const float*)d_in[23]; const float* zb2=(const float*)d_in[24];
    const float* sg =(const float*)d_in[25]; const float* sb =(const float*)d_in[26];
    float* out = (float*)d_out;

    float *p_z, *p_zmid, *p_a1, *p_Dp, *p_bt, *p_fbT, *p_zero, *p_C;
    __nv_bfloat16 *p_A, *p_B;
    cudaGetSymbolAddress((void**)&p_z,    g_z);
    cudaGetSymbolAddress((void**)&p_zmid, g_zmid);
    cudaGetSymbolAddress((void**)&p_a1,   g_a1);
    cudaGetSymbolAddress((void**)&p_Dp,   g_Dp);
    cudaGetSymbolAddress((void**)&p_bt,   g_bt);
    cudaGetSymbolAddress((void**)&p_fbT,  g_fb4T);
    cudaGetSymbolAddress((void**)&p_zero, g_zero);
    cudaGetSymbolAddress((void**)&p_C,    g_C);
    cudaGetSymbolAddress((void**)&p_A,    g_Asp);
    cudaGetSymbolAddress((void**)&p_B,    g_Bsp);

    const int DSM = 98432;
    cudaFuncSetAttribute(k_tc, cudaFuncAttributeMaxDynamicSharedMemorySize, DSM);

    // prep
    k_packW  <<<65536, 256>>>(fW4);
    k_packfbT<<<256, 256>>>(fb4);
    k_logsig <<<128, 256>>>(x);
    k_lnorm  <<<8192, 256>>>(sg, sb);
    k_spline <<<232, 128>>>();
    k_packD  <<<16128, 256>>>();
    k_gemm   <<<dim3(4,1008), 256>>>(p_Dp, p_fbT, p_zero, p_bt, 256, 256);
    k_h0     <<<128, 256>>>(x, hW1, hb1, hW2, hb2);

    for (int chunk = 0; chunk < 9; chunk++){
        k_tc<<<dim3(CH_ROWS/128, 512), 256, DSM>>>(
            p_A + (size_t)chunk*CH_ROWS*704, p_B, p_C);
        for (int s = 0; s < CH_STEPS; s++){
            int n = chunk*CH_STEPS + s;
            int jg0 = (2*n)*128,     jl0 = (2*s)*128;
            int jg1 = (2*n + 1)*128, jl1 = (2*s + 1)*128;
            // eval 1: k1 = g(z, d_knot); zmid = z + 0.5h k1
            k_f1<<<128, 256>>>(fW1, fb1, g1, be1, p_z, p_a1);
            k_f2<<<128, 256>>>(fW2, fb2, g2, be2, fW3, fb3, p_C, p_bt, p_a1,
                               p_z, p_zmid, jl0, jg0, 0.5f*HSTEP);
            // eval 2: z = z + h * g(zmid, d_mid)
            k_f1<<<128, 256>>>(fW1, fb1, g1, be1, p_zmid, p_a1);
            k_f2<<<128, 256>>>(fW2, fb2, g2, be2, fW3, fb3, p_C, p_bt, p_a1,
                               p_z, p_z, jl1, jg1, HSTEP);
        }
    }
    k_head<<<128, 256>>>(yW1, yb1, yW2, yb2, zW1, zb1, zW2, zb2, out);
}

// round 10
// speedup vs baseline: 2.1590x; 1.0563x over previous
#include <cuda_runtime.h>
#include <cuda_bf16.h>
#include <cstdint>

#define HSTEP (1.0f/63.0f)
#define CH_STEPS 7
#define CH_ROWS  1792

// ---------------- scratch ----------------
static __device__ float g_lsraw[128*64*231];
static __device__ float g_y[128*64*232];
static __device__ float g_dknot[63*232*128];
static __device__ float g_dmid [63*232*128];
static __device__ float g_z[128*256];
// precompute path
static __device__ __nv_bfloat16 g_Asp[(size_t)16128*704];
static __device__ __nv_bfloat16 g_Bsp[(size_t)65536*704];
static __device__ float g_Dp [(size_t)16128*256];
static __device__ float g_bt [(size_t)16128*256];
static __device__ float g_fb4T[256*256];
static __device__ float g_zero[256];
static __device__ float g_C[(size_t)CH_ROWS*65536];   // 470 MB ring chunk

// ---------------- helpers ----------------
__device__ __forceinline__ float2 ffma2(float2 a, float2 b, float2 c){
    unsigned long long au, bu, cu, du;
    au = *reinterpret_cast<unsigned long long*>(&a);
    bu = *reinterpret_cast<unsigned long long*>(&b);
    cu = *reinterpret_cast<unsigned long long*>(&c);
    asm("fma.rn.f32x2 %0,%1,%2,%3;" : "=l"(du) : "l"(au), "l"(bu), "l"(cu));
    return *reinterpret_cast<float2*>(&du);
}

__device__ __forceinline__ uint32_t smem_u32(const void* p){
    uint32_t a;
    asm("{ .reg .u64 t; cvta.to.shared.u64 t, %1; cvt.u32.u64 %0, t; }"
        : "=r"(a) : "l"(p));
    return a;
}

__device__ __forceinline__ void ldsm4(uint32_t* r, uint32_t addr){
    asm volatile("ldmatrix.sync.aligned.m8n8.x4.shared.b16 {%0,%1,%2,%3}, [%4];"
        : "=r"(r[0]), "=r"(r[1]), "=r"(r[2]), "=r"(r[3]) : "r"(addr));
}

__device__ __forceinline__ void mma_bf16(float* c, const uint32_t* a, const uint32_t* b){
    asm volatile("mma.sync.aligned.m16n8k16.row.col.f32.bf16.bf16.f32 "
        "{%0,%1,%2,%3}, {%4,%5,%6,%7}, {%8,%9}, {%0,%1,%2,%3};"
        : "+f"(c[0]), "+f"(c[1]), "+f"(c[2]), "+f"(c[3])
        : "r"(a[0]), "r"(a[1]), "r"(a[2]), "r"(a[3]), "r"(b[0]), "r"(b[1]));
}

__device__ __forceinline__ void cpasync16(uint32_t dst, const void* src){
    asm volatile("cp.async.cg.shared.global [%0], [%1], 16;" :: "r"(dst), "l"(src));
}

__device__ __forceinline__ void block_reduce_sum2(float& s, float& q){
    __shared__ float sh[64];
    const unsigned m = 0xffffffffu;
    #pragma unroll
    for (int off = 16; off; off >>= 1){
        s += __shfl_down_sync(m, s, off);
        q += __shfl_down_sync(m, q, off);
    }
    int w = threadIdx.x >> 5, l = threadIdx.x & 31;
    if (l == 0){ sh[w] = s; sh[32+w] = q; }
    __syncthreads();
    if (threadIdx.x == 0){
        float ts = 0.f, tq = 0.f;
        int nw = blockDim.x >> 5;
        for (int i = 0; i < nw; i++){ ts += sh[i]; tq += sh[32+i]; }
        sh[0] = ts; sh[32] = tq;
    }
    __syncthreads();
    s = sh[0]; q = sh[32];
}

// ---- 1) depth-2 log-signature ----
__global__ void k_logsig(const float* __restrict__ x){
    int b = blockIdx.x;
    __shared__ float psh[64*21];
    for (int idx = threadIdx.x; idx < 64*21; idx += blockDim.x){
        int n = idx / 21, i = idx % 21;
        psh[idx] = (i == 0) ? (float)n * HSTEP : x[(b*64 + n)*20 + (i-1)];
    }
    __syncthreads();
    int ch = threadIdx.x;
    if (ch < 21){
        for (int n = 0; n < 64; n++)
            g_lsraw[((size_t)b*64 + n)*231 + ch] = psh[n*21 + ch];
    } else if (ch < 231){
        int pp = ch - 21, i = 0, rem = pp;
        while (rem >= 20 - i){ rem -= 20 - i; i++; }
        int j = i + 1 + rem;
        float acc = 0.f, pip = 0.f, pjp = 0.f;
        for (int n = 0; n < 64; n++){
            float pi = psh[n*21 + i], pj = psh[n*21 + j];
            acc += 0.5f*(pip*(pj - pjp) - (pi - pip)*pjp);
            g_lsraw[((size_t)b*64 + n)*231 + ch] = acc;
            pip = pi; pjp = pj;
        }
    }
}

// ---- 2) sig_norm LN + control y ----
__global__ void k_lnorm(const float* __restrict__ sg, const float* __restrict__ sb){
    int r = blockIdx.x, t = threadIdx.x;
    float v = (t < 231) ? g_lsraw[(size_t)r*231 + t] : 0.f;
    float s = v, q = v*v;
    block_reduce_sum2(s, q);
    float mean = s*(1.0f/231.0f);
    float var  = q*(1.0f/231.0f) - mean*mean;
    float rstd = rsqrtf(var + 1e-5f);
    if (t < 231) g_y[(size_t)r*232 + 1 + t] = (v - mean)*rstd*sg[t] + sb[t];
    if (t == 0)  g_y[(size_t)r*232] = (float)(r & 63) * HSTEP;
}

// ---- 3) natural cubic spline derivatives ----
__global__ void k_spline(){
    __shared__ float cpS[64], idS[64];
    int t = threadIdx.x;
    if (t == 0){
        double ad = (1.0/63.0)/6.0, bd = 2.0*(1.0/63.0)/3.0, cprev = 0.0;
        for (int i = 1; i <= 62; i++){
            double den = bd - ad*cprev, cp = ad/den;
            cpS[i] = (float)cp; idS[i] = (float)(1.0/den); cprev = cp;
        }
    }
    __syncthreads();
    int g = blockIdx.x*128 + t;
    int b = g / 232, c = g % 232;
    float yv[64], M[64];
    for (int n = 0; n < 64; n++) yv[n] = g_y[((size_t)b*64 + n)*232 + c];
    const float ad = HSTEP/6.0f;
    M[0] = 0.f; M[63] = 0.f;
    float prev = 0.f;
    for (int i = 1; i <= 62; i++){
        float rhs = (yv[i+1] - 2.f*yv[i] + yv[i-1]) * 63.0f;
        prev = (rhs - ad*prev) * idS[i];
        M[i] = prev;
    }
    for (int i = 61; i >= 1; i--) M[i] -= cpS[i]*M[i+1];
    for (int n = 0; n < 63; n++){
        float dy = (yv[n+1] - yv[n]) * 63.0f;
        size_t o = ((size_t)n*232 + c)*128 + b;
        g_dknot[o] = dy - (HSTEP/6.0f) *(2.f*M[n] + M[n+1]);
        g_dmid [o] = dy + (HSTEP/24.0f)*(M[n] - M[n+1]);
    }
}

// ---- pack kernels ----
__global__ void k_packD(){
    int j = blockIdx.x, c = threadIdx.x;
    int n = j >> 8, e = (j >> 7) & 1, b = j & 127;
    const float* src = e ? g_dmid : g_dknot;
    if (c < 232){
        float v = src[((size_t)n*232 + c)*128 + b];
        __nv_bfloat16 h = __float2bfloat16(v);
        float hf = __bfloat162float(h);
        __nv_bfloat16 l = __float2bfloat16(v - hf);
        g_Asp[(size_t)j*704 + c]       = h;
        g_Asp[(size_t)j*704 + 232 + c] = h;
        g_Asp[(size_t)j*704 + 464 + c] = l;
        g_Dp[(size_t)j*256 + c] = v;
    } else {
        if (c < 240) g_Asp[(size_t)j*704 + 696 + (c - 232)] = __float2bfloat16(0.f);
        g_Dp[(size_t)j*256 + c] = 0.f;
    }
}

__global__ void k_packW(const float* __restrict__ fW4){
    int nrow = blockIdx.x, c = threadIdx.x;
    if (c < 232){
        float v = fW4[(size_t)nrow*232 + c];
        __nv_bfloat16 h = __float2bfloat16(v);
        float hf = __bfloat162float(h);
        __nv_bfloat16 l = __float2bfloat16(v - hf);
        g_Bsp[(size_t)nrow*704 + c]       = h;
        g_Bsp[(size_t)nrow*704 + 232 + c] = l;
        g_Bsp[(size_t)nrow*704 + 464 + c] = h;
    } else if (c < 240){
        g_Bsp[(size_t)nrow*704 + 696 + (c - 232)] = __float2bfloat16(0.f);
    }
}

__global__ void k_packfbT(const float* __restrict__ fb4){
    int c = blockIdx.x, h = threadIdx.x;
    g_fb4T[c*256 + h] = (c < 232) ? fb4[(size_t)h*232 + c] : 0.f;
}

// ---- 4) initial hidden state ----
__global__ void k_h0(const float* __restrict__ x,  const float* __restrict__ hW1,
                     const float* __restrict__ hb1, const float* __restrict__ hW2,
                     const float* __restrict__ hb2){
    int b = blockIdx.x, t = threadIdx.x;
    __shared__ float x0[20];
    __shared__ float hid[256];
    if (t < 20) x0[t] = x[(size_t)b*64*20 + t];
    __syncthreads();
    float s = hb1[t];
    for (int d = 0; d < 20; d++) s = fmaf(x0[d], hW1[d*256 + t], s);
    hid[t] = fmaxf(s, 0.f);
    __syncthreads();
    float s2 = hb2[t];
    for (int k = 0; k < 256; k++) s2 = fmaf(hid[k], hW2[k*256 + t], s2);
    g_z[b*256 + t] = s2;
}

// ---- generic tiled GEMM (bias-term precompute only) ----
__global__ void __launch_bounds__(256) k_gemm(
    const float* __restrict__ in, const float* __restrict__ W,
    const float* __restrict__ bias, float* __restrict__ out,
    int K, int Nout)
{
    __shared__ float wsh[2048];
    __shared__ float ish[512];
    int n0 = blockIdx.x*64, b0 = blockIdx.y*16;
    int t = threadIdx.x, bi = t >> 4, ng = t & 15;
    float4 bia = *(const float4*)(bias + n0 + ng*4);
    float2 acc0 = make_float2(bia.x, bia.y);
    float2 acc1 = make_float2(bia.z, bia.w);
    for (int k0 = 0; k0 < K; k0 += 32){
        __syncthreads();
        #pragma unroll
        for (int j = 0; j < 8; j++){
            int e = t + j*256;
            wsh[e] = W[(size_t)(k0 + (e >> 6))*Nout + n0 + (e & 63)];
        }
        #pragma unroll
        for (int j = 0; j < 2; j++){
            int e = t + j*256;
            ish[e] = in[(size_t)(b0 + (e >> 5))*K + k0 + (e & 31)];
        }
        __syncthreads();
        #pragma unroll
        for (int kk = 0; kk < 32; kk++){
            float zv = ish[bi*32 + kk];
            float2 zz = make_float2(zv, zv);
            const float2* wp = (const float2*)(wsh + kk*64 + ng*4);
            acc0 = ffma2(zz, wp[0], acc0);
            acc1 = ffma2(zz, wp[1], acc1);
        }
    }
    float4 o = make_float4(acc0.x, acc0.y, acc1.x, acc1.y);
    *(float4*)(out + (size_t)(b0 + bi)*Nout + n0 + ng*4) = o;
}

// ---- big GEMM on HMMA: C[1792 x 65536] = Asp_chunk @ Bspᵀ, K=704 ----
__global__ void __launch_bounds__(256, 2) k_tc(
    const __nv_bfloat16* __restrict__ A, const __nv_bfloat16* __restrict__ Bm,
    float* __restrict__ C)
{
    extern __shared__ __align__(128) char dsm[];
    uint32_t base = (smem_u32(dsm) + 127u) & ~127u;
    int t = threadIdx.x, lane = t & 31, warp = t >> 5;
    int mw = warp & 1, nw = warp >> 1;
    size_t j0 = (size_t)blockIdx.x * 128, n0 = (size_t)blockIdx.y * 128;
    const char* Ab = (const char*)A  + j0*1408;
    const char* Bb = (const char*)Bm + n0*1408;

    auto stg = [&](int ck, int s){
        uint32_t sb = base + s*32768u;
        #pragma unroll
        for (int i = 0; i < 4; i++){
            int e = t*4 + i;
            int row = e >> 3, q = e & 7;
            uint32_t d = sb + row*128 + ((q ^ (row & 7)) << 4);
            cpasync16(d, Ab + (size_t)row*1408 + ck*128 + q*16);
        }
        #pragma unroll
        for (int i = 0; i < 4; i++){
            int e = t*4 + i;
            int row = e >> 3, q = e & 7;
            uint32_t d = sb + 16384u + row*128 + ((q ^ (row & 7)) << 4);
            cpasync16(d, Bb + (size_t)row*1408 + ck*128 + q*16);
        }
        asm volatile("cp.async.commit_group;" ::: "memory");
    };

    float acc[4][4][4];
    #pragma unroll
    for (int mi = 0; mi < 4; mi++)
        #pragma unroll
        for (int ni = 0; ni < 4; ni++)
            #pragma unroll
            for (int r = 0; r < 4; r++) acc[mi][ni][r] = 0.f;

    stg(0, 0); stg(1, 1); stg(2, 2);

    for (int ck = 0; ck < 11; ck++){
        if (ck < 8) asm volatile("cp.async.wait_group 2;" ::: "memory");
        else        asm volatile("cp.async.wait_group 0;" ::: "memory");
        __syncthreads();
        uint32_t sA = base + (uint32_t)(ck % 3)*32768u;
        uint32_t sB = sA + 16384u;
        #pragma unroll
        for (int kk = 0; kk < 4; kk++){
            uint32_t afr[4][4], bfr[2][4];
            #pragma unroll
            for (int mi = 0; mi < 4; mi++){
                int row = mw*64 + mi*16 + (lane & 15);
                int q = kk*2 + (lane >> 4);
                ldsm4(afr[mi], sA + row*128 + ((q ^ (row & 7)) << 4));
            }
            #pragma unroll
            for (int nj = 0; nj < 2; nj++){
                int row = nw*32 + nj*16 + (lane & 7) + ((lane >> 4) & 1)*8;
                int q = kk*2 + ((lane >> 3) & 1);
                ldsm4(bfr[nj], sB + row*128 + ((q ^ (row & 7)) << 4));
            }
            #pragma unroll
            for (int mi = 0; mi < 4; mi++)
                #pragma unroll
                for (int ni = 0; ni < 4; ni++)
                    mma_bf16(acc[mi][ni], afr[mi], &bfr[ni >> 1][(ni & 1)*2]);
        }
        __syncthreads();
        if (ck + 3 < 11) stg(ck + 3, ck % 3);
    }

    #pragma unroll
    for (int mi = 0; mi < 4; mi++){
        size_t r0 = j0 + mw*64 + mi*16 + (lane >> 2);
        float* row0 = C + r0*65536 + n0 + nw*32 + (lane & 3)*2;
        float* row1 = row0 + (size_t)8*65536;
        #pragma unroll
        for (int ni = 0; ni < 4; ni++){
            *(float2*)(row0 + ni*8) = make_float2(acc[mi][ni][0], acc[mi][ni][1]);
            *(float2*)(row1 + ni*8) = make_float2(acc[mi][ni][2], acc[mi][ni][3]);
        }
    }
}

// ---- persistent scan over one chunk: 7 steps x 2 evals, block per batch ----
__global__ void __launch_bounds__(256) k_scan(
    const float* __restrict__ fW1, const float* __restrict__ fb1,
    const float* __restrict__ g1,  const float* __restrict__ be1,
    const float* __restrict__ fW2, const float* __restrict__ fb2,
    const float* __restrict__ g2,  const float* __restrict__ be2,
    const float* __restrict__ fW3, const float* __restrict__ fb3,
    const float* __restrict__ C,   const float* __restrict__ bt,
    float* __restrict__ zg, int jgbase)
{
    int b = blockIdx.x, t = threadIdx.x;
    __shared__ float zsh[256], zmid[256];
    __shared__ __align__(16) float a1sh[1024];
    __shared__ float a2sh[256], a3sh[256];
    __shared__ float2 red2[256];

    zsh[t] = zg[b*256 + t];
    __syncthreads();

    for (int s = 0; s < CH_STEPS; s++){
        #pragma unroll
        for (int e = 0; e < 2; e++){
            const float* zin = e ? zmid : zsh;
            // ---- GEMM1: a1 = relu(LN(z @ fW1 + fb1)), thread => cols 4t..4t+3
            float4 bv = __ldg((const float4*)fb1 + t);
            float2 A0 = make_float2(bv.x, bv.y);
            float2 A1 = make_float2(bv.z, bv.w);
            #pragma unroll 4
            for (int k = 0; k < 256; k++){
                float zv = zin[k];
                float2 zz = make_float2(zv, zv);
                float4 w = __ldg((const float4*)(fW1 + (size_t)k*1024) + t);
                A0 = ffma2(zz, make_float2(w.x, w.y), A0);
                A1 = ffma2(zz, make_float2(w.z, w.w), A1);
            }
            float ss = A0.x + A0.y + A1.x + A1.y;
            float qq = A0.x*A0.x + A0.y*A0.y + A1.x*A1.x + A1.y*A1.y;
            block_reduce_sum2(ss, qq);
            float mean = ss*(1.0f/1024.0f), var = qq*(1.0f/1024.0f) - mean*mean;
            float rstd = rsqrtf(var + 1e-5f);
            {
                float4 gg = __ldg((const float4*)g1 + t);
                float4 bb = __ldg((const float4*)be1 + t);
                float4 o;
                o.x = fmaxf((A0.x - mean)*rstd*gg.x + bb.x, 0.f);
                o.y = fmaxf((A0.y - mean)*rstd*gg.y + bb.y, 0.f);
                o.z = fmaxf((A1.x - mean)*rstd*gg.z + bb.z, 0.f);
                o.w = fmaxf((A1.y - mean)*rstd*gg.w + bb.w, 0.f);
                ((float4*)a1sh)[t] = o;
            }
            __syncthreads();
            // ---- GEMM2 split-k: half = t>>7 covers 512 k for outputs (2p,2p+1)
            int half = t >> 7, p = t & 127;
            float2 acc = make_float2(0.f, 0.f);
            const float* wb = fW2 + (size_t)half*512*256 + 2*p;
            const float* ab = a1sh + half*512;
            #pragma unroll 8
            for (int k = 0; k < 512; k++){
                float av = ab[k];
                float2 w = __ldg((const float2*)(wb + (size_t)k*256));
                acc = ffma2(make_float2(av, av), w, acc);
            }
            red2[t] = acc;
            __syncthreads();
            float s2 = 0.f, q2 = 0.f;
            float2 tot = make_float2(0.f, 0.f);
            if (t < 128){
                float2 lo = red2[t], hi = red2[t + 128];
                float2 bv2 = __ldg((const float2*)fb2 + t);
                tot = make_float2(lo.x + hi.x + bv2.x, lo.y + hi.y + bv2.y);
                s2 = tot.x + tot.y; q2 = tot.x*tot.x + tot.y*tot.y;
            }
            block_reduce_sum2(s2, q2);
            float mean2 = s2*(1.0f/256.0f), var2 = q2*(1.0f/256.0f) - mean2*mean2;
            float rstd2 = rsqrtf(var2 + 1e-5f);
            if (t < 128){
                float2 gg = __ldg((const float2*)g2 + t);
                float2 bb = __ldg((const float2*)be2 + t);
                a2sh[2*t]   = fmaxf((tot.x - mean2)*rstd2*gg.x + bb.x, 0.f);
                a2sh[2*t+1] = fmaxf((tot.y - mean2)*rstd2*gg.y + bb.y, 0.f);
            }
            __syncthreads();
            // ---- GEMM3: a3 = relu(a2 @ fW3 + fb3)
            float acc3 = __ldg(fb3 + t);
            #pragma unroll 8
            for (int k = 0; k < 256; k++)
                acc3 = fmaf(a2sh[k], __ldg(fW3 + (size_t)k*256 + t), acc3);
            a3sh[t] = fmaxf(acc3, 0.f);
            __syncthreads();
            // ---- C dot + z update
            int rloc = (2*s + e)*128 + b;
            const float* Crow = C + (size_t)rloc*65536 + t;
            float g = __ldg(bt + (size_t)(jgbase + rloc)*256 + t);
            #pragma unroll 8
            for (int k = 0; k < 256; k++)
                g = fmaf(a3sh[k], __ldg(Crow + (size_t)k*256), g);
            if (e == 0) zmid[t] = zsh[t] + 0.5f*HSTEP*g;
            else        zsh[t] = zsh[t] + HSTEP*g;
            __syncthreads();
        }
    }
    zg[b*256 + t] = zsh[t];
}

// ---- output heads ----
__global__ void k_head(const float* __restrict__ yW1, const float* __restrict__ yb1,
                       const float* __restrict__ yW2, const float* __restrict__ yb2,
                       const float* __restrict__ zW1, const float* __restrict__ zb1,
                       const float* __restrict__ zW2, const float* __restrict__ zb2,
                       float* __restrict__ out){
    int b = blockIdx.x, t = threadIdx.x;
    __shared__ float hsh[256], t1[128], t2[256];
    hsh[t] = g_z[b*256 + t];
    __syncthreads();
    float s = zb1[t];
    for (int k = 0; k < 256; k++) s = fmaf(hsh[k], zW1[k*256 + t], s);
    t2[t] = fmaxf(s, 0.f);
    if (t < 128){
        float s1 = yb1[t];
        for (int k = 0; k < 256; k++) s1 = fmaf(hsh[k], yW1[k*128 + t], s1);
        t1[t] = fmaxf(s1, 0.f);
    }
    __syncthreads();
    if (t == 0){
        float y = yb2[0];
        for (int j = 0; j < 128; j++) y = fmaf(t1[j], yW2[j], y);
        out[b] = y;
    }
    if (t < 20){
        float zz = zb2[t];
        for (int k = 0; k < 256; k++) zz = fmaf(t2[k], zW2[k*20 + t], zz);
        out[128 + b*20 + t] = zz;
    }
    out[128 + 2560 + b*256 + t] = hsh[t];
}

extern "C" void kernel_launch(void* const* d_in, const int* in_sizes, int n_in,
                              void* d_out, int out_size){
    const float* x  =(const float*)d_in[0];
    const float* hW1=(const float*)d_in[1]; const float* hb1=(const float*)d_in[2];
    const float* hW2=(const float*)d_in[3]; const float* hb2=(const float*)d_in[4];
    const float* fW1=(const float*)d_in[5]; const float* fb1=(const float*)d_in[6];
    const float* g1 =(const float*)d_in[7]; const float* be1=(const float*)d_in[8];
    const float* fW2=(const float*)d_in[9]; const float* fb2=(const float*)d_in[10];
    const float* g2 =(const float*)d_in[11]; const float* be2=(const float*)d_in[12];
    const float* fW3=(const float*)d_in[13]; const float* fb3=(const float*)d_in[14];
    const float* fW4=(const float*)d_in[15]; const float* fb4=(const float*)d_in[16];
    const float* yW1=(const float*)d_in[17]; const float* yb1=(const float*)d_in[18];
    const float* yW2=(const float*)d_in[19]; const float* yb2=(const float*)d_in[20];
    const float* zW1=(const float*)d_in[21]; const float* zb1=(const float*)d_in[22];
    const float* zW2=(const float*)d_in[23]; const float* zb2=(const float*)d_in[24];
    const float* sg =(const float*)d_in[25]; const float* sb =(const float*)d_in[26];
    float* out = (float*)d_out;

    float *p_z, *p_Dp, *p_bt, *p_fbT, *p_zero, *p_C;
    __nv_bfloat16 *p_A, *p_B;
    cudaGetSymbolAddress((void**)&p_z,    g_z);
    cudaGetSymbolAddress((void**)&p_Dp,   g_Dp);
    cudaGetSymbolAddress((void**)&p_bt,   g_bt);
    cudaGetSymbolAddress((void**)&p_fbT,  g_fb4T);
    cudaGetSymbolAddress((void**)&p_zero, g_zero);
    cudaGetSymbolAddress((void**)&p_C,    g_C);
    cudaGetSymbolAddress((void**)&p_A,    g_Asp);
    cudaGetSymbolAddress((void**)&p_B,    g_Bsp);

    const int DSM = 98432;
    cudaFuncSetAttribute(k_tc, cudaFuncAttributeMaxDynamicSharedMemorySize, DSM);

    // prep
    k_packW  <<<65536, 256>>>(fW4);
    k_packfbT<<<256, 256>>>(fb4);
    k_logsig <<<128, 256>>>(x);
    k_lnorm  <<<8192, 256>>>(sg, sb);
    k_spline <<<232, 128>>>();
    k_packD  <<<16128, 256>>>();
    k_gemm   <<<dim3(4,1008), 256>>>(p_Dp, p_fbT, p_zero, p_bt, 256, 256);
    k_h0     <<<128, 256>>>(x, hW1, hb1, hW2, hb2);

    for (int chunk = 0; chunk < 9; chunk++){
        k_tc<<<dim3(CH_ROWS/128, 512), 256, DSM>>>(
            p_A + (size_t)chunk*CH_ROWS*704, p_B, p_C);
        k_scan<<<128, 256>>>(fW1, fb1, g1, be1, fW2, fb2, g2, be2,
                             fW3, fb3, p_C, p_bt, p_z, chunk*CH_ROWS);
    }
    k_head<<<128, 256>>>(yW1, yb1, yW2, yb2, zW1, zb1, zW2, zb2, out);
}